// round 7
// baseline (speedup 1.0000x reference)
#include <cuda_runtime.h>
#include <cuda_fp16.h>
#include <mma.h>
#include <cstdint>
#include <cstddef>

using namespace nvcuda;

// ---------------- problem constants ----------------
#define Dc     1024
#define DFFc   4096
#define Ec     16
#define TKc    4
#define STEPSc 4
#define Tc     2048
#define RMAXc  (Tc*TKc)
#define PEREXP (DFFc*Dc)

// ---------------- device scratch ----------------
__device__ signed char g_w1q[(size_t)Ec*DFFc*Dc];   // ternary int8, 64MB
__device__ signed char g_w2q[(size_t)Ec*DFFc*Dc];   // 64MB
__device__ float  g_gateq[Ec*Dc];
__device__ float  g_g1[Ec];
__device__ float  g_g2[Ec];
__device__ float  g_part[32*1024];
__device__ float  g_state[Tc*Dc];
__device__ __half g_ctx_hi[Tc*Dc];
__device__ __half g_ctx_lo[Tc*Dc];
__device__ __half g_h_hi[(size_t)RMAXc*DFFc];
__device__ __half g_h_lo[(size_t)RMAXc*DFFc];
__device__ float  g_osl[(size_t)RMAXc*Dc];
__device__ int    g_list[Ec*Tc];
__device__ int    g_sel[Tc*TKc];
__device__ int    g_cnt[Ec];
__device__ int    g_off[Ec];

// ---------------- async-copy helpers ----------------
__device__ __forceinline__ uint32_t s2u(const void* p) {
    return (uint32_t)__cvta_generic_to_shared(p);
}
#define CP16(dst, src) \
    asm volatile("cp.async.cg.shared.global [%0], [%1], 16;" \
                 :: "r"(dst), "l"((const void*)(src)) : "memory")
#define CP_COMMIT() asm volatile("cp.async.commit_group;" ::: "memory")
#define CP_WAIT2()  asm volatile("cp.async.wait_group 2;" ::: "memory")

// ---------------- small utility kernels ----------------
__global__ void copy_in_kernel(const float* __restrict__ x) {
    int i = blockIdx.x * blockDim.x + threadIdx.x;
    if (i < Tc*Dc) g_state[i] = x[i];
}
__global__ void copy_out_kernel(float* __restrict__ out) {
    int i = blockIdx.x * blockDim.x + threadIdx.x;
    if (i < Tc*Dc) out[i] = g_state[i];
}
__global__ void zero_cnt_kernel() { if (threadIdx.x < Ec) g_cnt[threadIdx.x] = 0; }

__global__ void offsets_kernel() {
    if (threadIdx.x == 0) {
        int r = 0;
        for (int e = 0; e < Ec; e++) { g_off[e] = r; r += g_cnt[e]; }
    }
}

// ---------------- quantization ----------------
__global__ void abs_partial_kernel(const float* __restrict__ w1, const float* __restrict__ w2) {
    int chunk = blockIdx.x;
    int tn    = blockIdx.y;
    const float* base = (tn < Ec) ? (w1 + (size_t)tn * PEREXP)
                                  : (w2 + (size_t)(tn - Ec) * PEREXP);
    base += (size_t)chunk * 4096;
    int tid = threadIdx.x;
    float s = 0.f;
    #pragma unroll
    for (int i = 0; i < 16; i++) s += fabsf(base[tid + i*256]);
    __shared__ float red[256];
    red[tid] = s; __syncthreads();
    for (int st = 128; st > 0; st >>= 1) { if (tid < st) red[tid] += red[tid+st]; __syncthreads(); }
    if (tid == 0) g_part[tn*1024 + chunk] = red[0];
}

__global__ void scales_kernel() {
    int tn = blockIdx.x;
    int tid = threadIdx.x;
    float s = 0.f;
    for (int i = tid; i < 1024; i += 256) s += g_part[tn*1024 + i];
    __shared__ float red[256];
    red[tid] = s; __syncthreads();
    for (int st = 128; st > 0; st >>= 1) { if (tid < st) red[tid] += red[tid+st]; __syncthreads(); }
    if (tid == 0) {
        float g = fmaxf(red[0] / (float)PEREXP, 1e-5f);
        if (tn < Ec) g_g1[tn] = g; else g_g2[tn - Ec] = g;
    }
}

__global__ void gate_kernel(const float* __restrict__ gw) {
    int tid = threadIdx.x;
    float s = 0.f;
    for (int i = tid; i < Ec*Dc; i += 256) s += fabsf(gw[i]);
    __shared__ float red[256];
    __shared__ float sg;
    red[tid] = s; __syncthreads();
    for (int st = 128; st > 0; st >>= 1) { if (tid < st) red[tid] += red[tid+st]; __syncthreads(); }
    if (tid == 0) sg = fmaxf(red[0] / (float)(Ec*Dc), 1e-5f);
    __syncthreads();
    float g = sg;
    for (int i = tid; i < Ec*Dc; i += 256) {
        float q = rintf(gw[i] / g);
        g_gateq[i] = fminf(fmaxf(q, -1.f), 1.f);
    }
}

__global__ void quantw_kernel(const float* __restrict__ w, int which) {
    signed char* q = which ? g_w2q : g_w1q;
    const float* gs = which ? g_g2 : g_g1;
    size_t nvec   = (size_t)Ec * PEREXP / 4;
    size_t stride = (size_t)gridDim.x * blockDim.x;
    for (size_t i = (size_t)blockIdx.x * blockDim.x + threadIdx.x; i < nvec; i += stride) {
        int e = (int)((i * 4) / (size_t)PEREXP);
        float g = gs[e];
        float4 v = reinterpret_cast<const float4*>(w)[i];
        int q0 = (int)fminf(fmaxf(rintf(v.x / g), -1.f), 1.f);
        int q1 = (int)fminf(fmaxf(rintf(v.y / g), -1.f), 1.f);
        int q2 = (int)fminf(fmaxf(rintf(v.z / g), -1.f), 1.f);
        int q3 = (int)fminf(fmaxf(rintf(v.w / g), -1.f), 1.f);
        uint32_t packed = (uint32_t)(q0 & 0xFF) | ((uint32_t)(q1 & 0xFF) << 8)
                        | ((uint32_t)(q2 & 0xFF) << 16) | ((uint32_t)(q3 & 0xFF) << 24);
        reinterpret_cast<uint32_t*>(q)[i] = packed;
    }
}

// ---------------- routing ----------------
__global__ void route_kernel(const float* __restrict__ comp, const float* __restrict__ temb, int step) {
    int t = blockIdx.x, tid = threadIdx.x;
    if (!(comp[t] > 0.5f)) {
        #pragma unroll
        for (int i = 0; i < 8; i++) {
            int d = tid + i*128;
            g_ctx_hi[t*Dc + d] = __float2half(0.f);
            g_ctx_lo[t*Dc + d] = __float2half(0.f);
        }
        return;
    }
    float cx[8];
    #pragma unroll
    for (int i = 0; i < 8; i++) {
        int d = tid + i*128;
        float v = g_state[t*Dc + d] + temb[step*Dc + d];
        cx[i] = v;
        __half hi = __float2half(v);
        g_ctx_hi[t*Dc + d] = hi;
        g_ctx_lo[t*Dc + d] = __float2half(v - __half2float(hi));
    }
    float p[16];
    #pragma unroll
    for (int e = 0; e < 16; e++) p[e] = 0.f;
    #pragma unroll
    for (int i = 0; i < 8; i++) {
        int d = tid + i*128;
        #pragma unroll
        for (int e = 0; e < 16; e++) p[e] += cx[i] * g_gateq[e*Dc + d];
    }
    __shared__ float wsum[4][16];
    __shared__ float slog[16];
    int lane = tid & 31, wp = tid >> 5;
    #pragma unroll
    for (int e = 0; e < 16; e++) {
        float s = p[e];
        for (int o = 16; o > 0; o >>= 1) s += __shfl_down_sync(0xffffffffu, s, o);
        if (lane == 0) wsum[wp][e] = s;
    }
    __syncthreads();
    if (tid < 16) slog[tid] = wsum[0][tid] + wsum[1][tid] + wsum[2][tid] + wsum[3][tid];
    __syncthreads();
    if (tid == 0) {
        float lg[16];
        #pragma unroll
        for (int e = 0; e < 16; e++) lg[e] = slog[e];
        for (int k = 0; k < TKc; k++) {
            int best = 0; float bv = lg[0];
            for (int e = 1; e < 16; e++) if (lg[e] > bv) { bv = lg[e]; best = e; }
            g_sel[t*TKc + k] = best;
            lg[best] = -3.4e38f;
            int pos = atomicAdd(&g_cnt[best], 1);
            g_list[best*Tc + pos] = t*TKc + k;
        }
    }
}

// ==================================================================
// wmma GEMM, 64(M) x 128(N) block tile, K-chunk 64, 3-stage cp.async
// Weights staged as INT8 ternary (halved traffic; W-int8 fits L2),
// expanded to fp16 in a shared conversion buffer before MMA.
// Per stage: AsHi[64][72]h + AsLo[64][72]h + Bs8[128][80]b = 28 KB.
// 3 stages + Bh[128][72]h convert buffer = 102 KB -> 2 CTAs/SM.
// ==================================================================
#define A_BYTES     9216             // 64*72*2
#define B8_BYTES    10240            // 128*80 (int8, 16B-aligned rows)
#define STAGE_BYTES (2*A_BYTES + B8_BYTES)   // 28672
#define BH_OFF      (3*STAGE_BYTES)          // 86016
#define BH_BYTES    18432                    // 128*72*2 fp16
#define DSM_BYTES   (BH_OFF + BH_BYTES)      // 104448

// convert one stage's int8 B tile -> fp16 Bh (exact for {-1,0,1})
__device__ __forceinline__ void convert_b(char* dsm, int slot, int tid) {
    const uint32_t* src = (const uint32_t*)(dsm + (size_t)slot*STAGE_BYTES + 2*A_BYTES);
    __half* dst = (__half*)(dsm + BH_OFF);
    int r = tid >> 1, half = tid & 1;                 // 128 rows x 2 halves
    const uint32_t* s = src + (size_t)r*20 + half*8;  // 80B stride = 20 words
    __half hbuf[32];
    #pragma unroll
    for (int j = 0; j < 8; j++) {
        uint32_t w = s[j];
        hbuf[j*4+0] = __int2half_rn((int)(signed char)(w));
        hbuf[j*4+1] = __int2half_rn((int)(signed char)(w >> 8));
        hbuf[j*4+2] = __int2half_rn((int)(signed char)(w >> 16));
        hbuf[j*4+3] = __int2half_rn((int)(signed char)(w >> 24));
    }
    uint4* d = (uint4*)(dst + (size_t)r*72 + half*32);
    #pragma unroll
    for (int j = 0; j < 4; j++) d[j] = ((uint4*)hbuf)[j];
}

// ---------------- FFN1: H = gelu(g1 * ctx @ W1^T) ----------------
__global__ void __launch_bounds__(256) ffn1_kernel() {
    extern __shared__ char dsm[];
    __shared__ int rowc[64];

    int e   = blockIdx.z;
    int cnt = g_cnt[e];
    int m0  = blockIdx.x * 64;
    if (m0 >= cnt) return;
    int n0  = blockIdx.y * 128;
    int tid = threadIdx.x;

    if (tid < 64) rowc[tid] = (m0 + tid < cnt) ? g_list[e*Tc + m0 + tid] : -1;
    __syncthreads();

    uint32_t sb = s2u(dsm);
    const signed char* W = g_w1q + (size_t)e*DFFc*Dc + (size_t)n0*Dc;

    auto stage = [&](int chunk, int slot) {
        int k0 = chunk << 6;
        uint32_t aHi = sb + (uint32_t)slot * STAGE_BYTES;
        uint32_t aLo = aHi + A_BYTES;
        uint32_t bS  = aLo + A_BYTES;
        #pragma unroll
        for (int it = 0; it < 2; it++) {          // A: 64x64 halves = 512 granules
            int u = tid + (it << 8);
            int r = u >> 3, gi = u & 7;
            uint32_t off = (uint32_t)(r*144 + gi*16);
            int code = rowc[r];
            int tok = code >= 0 ? (code >> 2) : 0;
            CP16(aHi + off, g_ctx_hi + (size_t)tok*Dc + k0 + (gi<<3));
            CP16(aLo + off, g_ctx_lo + (size_t)tok*Dc + k0 + (gi<<3));
        }
        #pragma unroll
        for (int it = 0; it < 2; it++) {          // B int8: 128 rows x 64B = 512 granules
            int u = tid + (it << 8);
            int r = u >> 2, gi = u & 3;
            uint32_t off = (uint32_t)(r*80 + gi*16);
            CP16(bS + off, W + (size_t)r*Dc + k0 + (gi<<4));
        }
    };

    const int KC = Dc / 64;   // 16
    stage(0, 0); CP_COMMIT();
    stage(1, 1); CP_COMMIT();
    stage(2, 2); CP_COMMIT();

    int warp = tid >> 5;
    int wm = warp & 1, wn = warp >> 1;     // 2x4 warp grid, warp tile 32x32
    wmma::fragment<wmma::accumulator,16,16,16,float> acc[2][2];
    #pragma unroll
    for (int i = 0; i < 2; i++)
        #pragma unroll
        for (int j = 0; j < 2; j++) wmma::fill_fragment(acc[i][j], 0.f);

    for (int c = 0; c < KC; c++) {
        CP_WAIT2();
        __syncthreads();
        int slot = c % 3;
        convert_b(dsm, slot, tid);
        __syncthreads();
        __half* AsHi = (__half*)(dsm + (size_t)slot*STAGE_BYTES);
        __half* AsLo = (__half*)(dsm + (size_t)slot*STAGE_BYTES + A_BYTES);
        __half* Bs   = (__half*)(dsm + BH_OFF);
        #pragma unroll
        for (int kk = 0; kk < 64; kk += 16) {
            wmma::fragment<wmma::matrix_a,16,16,16,__half,wmma::row_major> aHi[2], aLo[2];
            wmma::fragment<wmma::matrix_b,16,16,16,__half,wmma::col_major> b[2];
            #pragma unroll
            for (int i = 0; i < 2; i++) {
                wmma::load_matrix_sync(aHi[i], AsHi + (size_t)(wm*32 + i*16)*72 + kk, 72);
                wmma::load_matrix_sync(aLo[i], AsLo + (size_t)(wm*32 + i*16)*72 + kk, 72);
            }
            #pragma unroll
            for (int j = 0; j < 2; j++)
                wmma::load_matrix_sync(b[j], Bs + (size_t)(wn*32 + j*16)*72 + kk, 72);
            #pragma unroll
            for (int i = 0; i < 2; i++)
                #pragma unroll
                for (int j = 0; j < 2; j++) {
                    wmma::mma_sync(acc[i][j], aHi[i], b[j], acc[i][j]);
                    wmma::mma_sync(acc[i][j], aLo[i], b[j], acc[i][j]);
                }
        }
        __syncthreads();
        if (c + 3 < KC) stage(c + 3, slot);
        CP_COMMIT();
    }

    // epilogue via smem (reuse stage memory): Cs[64][132]
    float* Cs = (float*)dsm;
    #pragma unroll
    for (int i = 0; i < 2; i++)
        #pragma unroll
        for (int j = 0; j < 2; j++)
            wmma::store_matrix_sync(Cs + (size_t)(wm*32 + i*16)*132 + wn*32 + j*16,
                                    acc[i][j], 132, wmma::mem_row_major);
    __syncthreads();

    float g1 = g_g1[e];
    int off  = g_off[e];
    for (int idx = tid; idx < 64*64; idx += 256) {
        int r = idx >> 6, cp = (idx & 63) << 1;
        if (rowc[r] < 0) continue;
        float v0 = g1 * Cs[(size_t)r*132 + cp];
        float v1 = g1 * Cs[(size_t)r*132 + cp + 1];
        float e0 = 0.5f * v0 * (1.0f + erff(v0 * 0.7071067811865476f));
        float e1 = 0.5f * v1 * (1.0f + erff(v1 * 0.7071067811865476f));
        __half h0 = __float2half(e0), h1 = __float2half(e1);
        size_t o = (size_t)(off + m0 + r)*DFFc + n0 + cp;
        *reinterpret_cast<__half2*>(&g_h_hi[o]) = __halves2half2(h0, h1);
        *reinterpret_cast<__half2*>(&g_h_lo[o]) =
            __halves2half2(__float2half(e0 - __half2float(h0)),
                           __float2half(e1 - __half2float(h1)));
    }
}

// ---------------- FFN2: O = g2 * H @ W2^T ----------------
__global__ void __launch_bounds__(256) ffn2_kernel() {
    extern __shared__ char dsm[];
    __shared__ int rowc[64];

    int e   = blockIdx.z;
    int cnt = g_cnt[e];
    int m0  = blockIdx.x * 64;
    if (m0 >= cnt) return;
    int n0  = blockIdx.y * 128;
    int tid = threadIdx.x;
    int off = g_off[e];

    if (tid < 64) rowc[tid] = (m0 + tid < cnt) ? g_list[e*Tc + m0 + tid] : -1;
    __syncthreads();

    uint32_t sb = s2u(dsm);
    const signed char* W = g_w2q + (size_t)e*DFFc*Dc + (size_t)n0*DFFc;
    int lastrow = off + cnt - 1;

    auto stage = [&](int chunk, int slot) {
        int k0 = chunk << 6;
        uint32_t aHi = sb + (uint32_t)slot * STAGE_BYTES;
        uint32_t aLo = aHi + A_BYTES;
        uint32_t bS  = aLo + A_BYTES;
        #pragma unroll
        for (int it = 0; it < 2; it++) {
            int u = tid + (it << 8);
            int r = u >> 3, gi = u & 7;
            uint32_t off2 = (uint32_t)(r*144 + gi*16);
            int src = off + m0 + r; if (src > lastrow) src = lastrow;
            CP16(aHi + off2, g_h_hi + (size_t)src*DFFc + k0 + (gi<<3));
            CP16(aLo + off2, g_h_lo + (size_t)src*DFFc + k0 + (gi<<3));
        }
        #pragma unroll
        for (int it = 0; it < 2; it++) {
            int u = tid + (it << 8);
            int r = u >> 2, gi = u & 3;
            uint32_t off2 = (uint32_t)(r*80 + gi*16);
            CP16(bS + off2, W + (size_t)r*DFFc + k0 + (gi<<4));
        }
    };

    const int KC = DFFc / 64;   // 64
    stage(0, 0); CP_COMMIT();
    stage(1, 1); CP_COMMIT();
    stage(2, 2); CP_COMMIT();

    int warp = tid >> 5;
    int wm = warp & 1, wn = warp >> 1;
    wmma::fragment<wmma::accumulator,16,16,16,float> acc[2][2];
    #pragma unroll
    for (int i = 0; i < 2; i++)
        #pragma unroll
        for (int j = 0; j < 2; j++) wmma::fill_fragment(acc[i][j], 0.f);

    for (int c = 0; c < KC; c++) {
        CP_WAIT2();
        __syncthreads();
        int slot = c % 3;
        convert_b(dsm, slot, tid);
        __syncthreads();
        __half* AsHi = (__half*)(dsm + (size_t)slot*STAGE_BYTES);
        __half* AsLo = (__half*)(dsm + (size_t)slot*STAGE_BYTES + A_BYTES);
        __half* Bs   = (__half*)(dsm + BH_OFF);
        #pragma unroll
        for (int kk = 0; kk < 64; kk += 16) {
            wmma::fragment<wmma::matrix_a,16,16,16,__half,wmma::row_major> aHi[2], aLo[2];
            wmma::fragment<wmma::matrix_b,16,16,16,__half,wmma::col_major> b[2];
            #pragma unroll
            for (int i = 0; i < 2; i++) {
                wmma::load_matrix_sync(aHi[i], AsHi + (size_t)(wm*32 + i*16)*72 + kk, 72);
                wmma::load_matrix_sync(aLo[i], AsLo + (size_t)(wm*32 + i*16)*72 + kk, 72);
            }
            #pragma unroll
            for (int j = 0; j < 2; j++)
                wmma::load_matrix_sync(b[j], Bs + (size_t)(wn*32 + j*16)*72 + kk, 72);
            #pragma unroll
            for (int i = 0; i < 2; i++)
                #pragma unroll
                for (int j = 0; j < 2; j++) {
                    wmma::mma_sync(acc[i][j], aHi[i], b[j], acc[i][j]);
                    wmma::mma_sync(acc[i][j], aLo[i], b[j], acc[i][j]);
                }
        }
        __syncthreads();
        if (c + 3 < KC) stage(c + 3, slot);
        CP_COMMIT();
    }

    float* Cs = (float*)dsm;
    #pragma unroll
    for (int i = 0; i < 2; i++)
        #pragma unroll
        for (int j = 0; j < 2; j++)
            wmma::store_matrix_sync(Cs + (size_t)(wm*32 + i*16)*132 + wn*32 + j*16,
                                    acc[i][j], 132, wmma::mem_row_major);
    __syncthreads();

    float g2 = g_g2[e];
    for (int idx = tid; idx < 64*128; idx += 256) {
        int r = idx >> 7, c2 = idx & 127;
        int sc = rowc[r];
        if (sc < 0) continue;
        g_osl[(size_t)sc*Dc + n0 + c2] = g2 * Cs[(size_t)r*132 + c2];
    }
}

// ---------------- combine ----------------
__global__ void combine_kernel(const float* __restrict__ comp, const float* __restrict__ normw) {
    int t = blockIdx.x, tid = threadIdx.x;
    if (!(comp[t] > 0.5f)) return;
    int se[4];
    #pragma unroll
    for (int k = 0; k < 4; k++) se[k] = g_sel[t*4 + k];
    int ord[4] = {0,1,2,3};
    #pragma unroll
    for (int a = 0; a < 3; a++)
        #pragma unroll
        for (int b = a+1; b < 4; b++)
            if (se[ord[b]] < se[ord[a]]) { int tmp = ord[a]; ord[a] = ord[b]; ord[b] = tmp; }
    float y[4]; float ss = 0.f;
    #pragma unroll
    for (int i = 0; i < 4; i++) {
        int d = tid + i*256;
        float s = g_osl[(size_t)(t*4 + ord[0])*Dc + d];
        s += g_osl[(size_t)(t*4 + ord[1])*Dc + d];
        s += g_osl[(size_t)(t*4 + ord[2])*Dc + d];
        s += g_osl[(size_t)(t*4 + ord[3])*Dc + d];
        float v = s + g_state[t*Dc + d];
        y[i] = v; ss += v*v;
    }
    int lane = tid & 31, wp = tid >> 5;
    for (int o = 16; o > 0; o >>= 1) ss += __shfl_down_sync(0xffffffffu, ss, o);
    __shared__ float ws[8];
    __shared__ float svar;
    if (lane == 0) ws[wp] = ss;
    __syncthreads();
    if (tid == 0) {
        float s2 = 0.f;
        for (int w = 0; w < 8; w++) s2 += ws[w];
        svar = s2 * (1.f / (float)Dc);
    }
    __syncthreads();
    float rinv = rsqrtf(svar + 1e-6f);
    #pragma unroll
    for (int i = 0; i < 4; i++) {
        int d = tid + i*256;
        g_state[t*Dc + d] = normw[d] * y[i] * rinv;
    }
}

// ---------------- launch ----------------
extern "C" void kernel_launch(void* const* d_in, const int* in_sizes, int n_in,
                              void* d_out, int out_size) {
    const float* x    = (const float*)d_in[0];
    const float* comp = (const float*)d_in[1];
    const float* gw   = (const float*)d_in[2];
    const float* w1   = (const float*)d_in[3];
    const float* w2   = (const float*)d_in[4];
    const float* temb = (const float*)d_in[5];
    const float* nw   = (const float*)d_in[6];
    float* out = (float*)d_out;

    cudaFuncSetAttribute(ffn1_kernel, cudaFuncAttributeMaxDynamicSharedMemorySize, DSM_BYTES);
    cudaFuncSetAttribute(ffn2_kernel, cudaFuncAttributeMaxDynamicSharedMemorySize, DSM_BYTES);

    copy_in_kernel<<<(Tc*Dc + 511)/512, 512>>>(x);

    abs_partial_kernel<<<dim3(1024, 32), 256>>>(w1, w2);
    scales_kernel<<<32, 256>>>();
    gate_kernel<<<1, 256>>>(gw);
    quantw_kernel<<<8192, 256>>>(w1, 0);
    quantw_kernel<<<8192, 256>>>(w2, 1);

    for (int s = 0; s < STEPSc; s++) {
        zero_cnt_kernel<<<1, 32>>>();
        route_kernel<<<Tc, 128>>>(comp, temb, s);
        offsets_kernel<<<1, 32>>>();
        ffn1_kernel<<<dim3(Tc/64, DFFc/128, Ec), 256, DSM_BYTES>>>();
        ffn2_kernel<<<dim3(Tc/64, Dc/128, Ec), 256, DSM_BYTES>>>();
        combine_kernel<<<Tc, 256>>>(comp, nw);
    }

    copy_out_kernel<<<(Tc*Dc + 511)/512, 512>>>(out);
}

// round 8
// speedup vs baseline: 1.1306x; 1.1306x over previous
#include <cuda_runtime.h>
#include <cuda_fp16.h>
#include <mma.h>
#include <cstdint>
#include <cstddef>

using namespace nvcuda;

// ---------------- problem constants ----------------
#define Dc     1024
#define DFFc   4096
#define Ec     16
#define TKc    4
#define STEPSc 4
#define Tc     2048
#define RMAXc  (Tc*TKc)
#define PEREXP (DFFc*Dc)
#define MBLK   16                    // m-blocks per expert (cap 1024 rows/expert)

// ---------------- device scratch ----------------
__device__ __half g_w1q[(size_t)Ec*DFFc*Dc];
__device__ __half g_w2q[(size_t)Ec*DFFc*Dc];
__device__ float  g_gateq[Ec*Dc];
__device__ float  g_g1[Ec];
__device__ float  g_g2[Ec];
__device__ float  g_part[32*1024];
__device__ float  g_state[Tc*Dc];
__device__ __half g_ctx_hi[Tc*Dc];
__device__ __half g_ctx_lo[Tc*Dc];
__device__ __half g_h_hi[(size_t)RMAXc*DFFc];
__device__ __half g_h_lo[(size_t)RMAXc*DFFc];
__device__ float  g_osl[(size_t)RMAXc*Dc];
__device__ int    g_list[Ec*Tc];
__device__ int    g_sel[Tc*TKc];
__device__ int    g_cnt[Ec];

// ---------------- small utility kernels ----------------
__global__ void copy_in_kernel(const float* __restrict__ x) {
    int i = blockIdx.x * blockDim.x + threadIdx.x;
    if (i < Tc*Dc) g_state[i] = x[i];
}
__global__ void copy_out_kernel(float* __restrict__ out) {
    int i = blockIdx.x * blockDim.x + threadIdx.x;
    if (i < Tc*Dc) out[i] = g_state[i];
}
__global__ void zero_cnt_kernel() { if (threadIdx.x < Ec) g_cnt[threadIdx.x] = 0; }

// ---------------- quantization ----------------
__global__ void abs_partial_kernel(const float* __restrict__ w1, const float* __restrict__ w2) {
    int chunk = blockIdx.x;
    int tn    = blockIdx.y;
    const float* base = (tn < Ec) ? (w1 + (size_t)tn * PEREXP)
                                  : (w2 + (size_t)(tn - Ec) * PEREXP);
    base += (size_t)chunk * 4096;
    int tid = threadIdx.x;
    float s = 0.f;
    #pragma unroll
    for (int i = 0; i < 16; i++) s += fabsf(base[tid + i*256]);
    __shared__ float red[256];
    red[tid] = s; __syncthreads();
    for (int st = 128; st > 0; st >>= 1) { if (tid < st) red[tid] += red[tid+st]; __syncthreads(); }
    if (tid == 0) g_part[tn*1024 + chunk] = red[0];
}

__global__ void scales_kernel() {
    int tn = blockIdx.x;
    int tid = threadIdx.x;
    float s = 0.f;
    for (int i = tid; i < 1024; i += 256) s += g_part[tn*1024 + i];
    __shared__ float red[256];
    red[tid] = s; __syncthreads();
    for (int st = 128; st > 0; st >>= 1) { if (tid < st) red[tid] += red[tid+st]; __syncthreads(); }
    if (tid == 0) {
        float g = fmaxf(red[0] / (float)PEREXP, 1e-5f);
        if (tn < Ec) g_g1[tn] = g; else g_g2[tn - Ec] = g;
    }
}

__global__ void gate_kernel(const float* __restrict__ gw) {
    int tid = threadIdx.x;
    float s = 0.f;
    for (int i = tid; i < Ec*Dc; i += 256) s += fabsf(gw[i]);
    __shared__ float red[256];
    __shared__ float sg;
    red[tid] = s; __syncthreads();
    for (int st = 128; st > 0; st >>= 1) { if (tid < st) red[tid] += red[tid+st]; __syncthreads(); }
    if (tid == 0) sg = fmaxf(red[0] / (float)(Ec*Dc), 1e-5f);
    __syncthreads();
    float g = sg;
    for (int i = tid; i < Ec*Dc; i += 256) {
        float q = rintf(gw[i] / g);
        g_gateq[i] = fminf(fmaxf(q, -1.f), 1.f);
    }
}

__global__ void quantw_kernel(const float* __restrict__ w, int which) {
    __half* q = which ? g_w2q : g_w1q;
    const float* gs = which ? g_g2 : g_g1;
    size_t nvec   = (size_t)Ec * PEREXP / 4;
    size_t stride = (size_t)gridDim.x * blockDim.x;
    for (size_t i = (size_t)blockIdx.x * blockDim.x + threadIdx.x; i < nvec; i += stride) {
        int e = (int)((i * 4) / (size_t)PEREXP);
        float g = gs[e];
        float4 v = reinterpret_cast<const float4*>(w)[i];
        float q0 = fminf(fmaxf(rintf(v.x / g), -1.f), 1.f);
        float q1 = fminf(fmaxf(rintf(v.y / g), -1.f), 1.f);
        float q2 = fminf(fmaxf(rintf(v.z / g), -1.f), 1.f);
        float q3 = fminf(fmaxf(rintf(v.w / g), -1.f), 1.f);
        __half2* qo = reinterpret_cast<__half2*>(q) + i*2;
        qo[0] = __floats2half2_rn(q0, q1);
        qo[1] = __floats2half2_rn(q2, q3);
    }
}

// ---------------- routing ----------------
__global__ void route_kernel(const float* __restrict__ comp, const float* __restrict__ temb, int step) {
    int t = blockIdx.x, tid = threadIdx.x;
    if (!(comp[t] > 0.5f)) {
        #pragma unroll
        for (int i = 0; i < 8; i++) {
            int d = tid + i*128;
            g_ctx_hi[t*Dc + d] = __float2half(0.f);
            g_ctx_lo[t*Dc + d] = __float2half(0.f);
        }
        return;
    }
    float cx[8];
    #pragma unroll
    for (int i = 0; i < 8; i++) {
        int d = tid + i*128;
        float v = g_state[t*Dc + d] + temb[step*Dc + d];
        cx[i] = v;
        __half hi = __float2half(v);
        g_ctx_hi[t*Dc + d] = hi;
        g_ctx_lo[t*Dc + d] = __float2half(v - __half2float(hi));
    }
    float p[16];
    #pragma unroll
    for (int e = 0; e < 16; e++) p[e] = 0.f;
    #pragma unroll
    for (int i = 0; i < 8; i++) {
        int d = tid + i*128;
        #pragma unroll
        for (int e = 0; e < 16; e++) p[e] += cx[i] * g_gateq[e*Dc + d];
    }
    __shared__ float wsum[4][16];
    __shared__ float slog[16];
    int lane = tid & 31, wp = tid >> 5;
    #pragma unroll
    for (int e = 0; e < 16; e++) {
        float s = p[e];
        for (int o = 16; o > 0; o >>= 1) s += __shfl_down_sync(0xffffffffu, s, o);
        if (lane == 0) wsum[wp][e] = s;
    }
    __syncthreads();
    if (tid < 16) slog[tid] = wsum[0][tid] + wsum[1][tid] + wsum[2][tid] + wsum[3][tid];
    __syncthreads();
    if (tid == 0) {
        float lg[16];
        #pragma unroll
        for (int e = 0; e < 16; e++) lg[e] = slog[e];
        for (int k = 0; k < TKc; k++) {
            int best = 0; float bv = lg[0];
            for (int e = 1; e < 16; e++) if (lg[e] > bv) { bv = lg[e]; best = e; }
            g_sel[t*TKc + k] = best;
            lg[best] = -3.4e38f;
            int pos = atomicAdd(&g_cnt[best], 1);
            g_list[best*Tc + pos] = t*TKc + k;
        }
    }
}

// ==================================================================
// wmma GEMM (R2 structure): 64(M) x 128(N) block, K-chunk 64,
// 8 warps 2(M)x4(N), warp tile 32x32, register-prefetch double buffer.
// Split-fp16 A: hi accumulated in f32, lo accumulated in f16 (2x rate
// if HW double-rates f16-acc HMMA; error contribution ~8e-8).
// smem 36KB -> 2 CTAs/SM.
// ==================================================================
#define SM_AHI 0
#define SM_ALO 9216
#define SM_B   18432
#define SM_BYTES 36864
#define CSH_OFF  34048               // f16 Cs at 34048 (f32 Cs is 64*132*4=33792)

// ---------------- FFN1: H = gelu(g1 * ctx @ W1^T) ----------------
__global__ void __launch_bounds__(256, 2) ffn1_kernel() {
    int e   = blockIdx.z;
    int cnt = g_cnt[e];
    int m0  = blockIdx.x * 64;
    if (m0 >= cnt) return;
    int n0  = blockIdx.y * 128;

    __shared__ __align__(16) char smem_raw[SM_BYTES + 64*136*2];
    __shared__ int rows[64];
    __shared__ int s_off;
    __half (*AsHi)[72] = (__half(*)[72])(smem_raw + SM_AHI);
    __half (*AsLo)[72] = (__half(*)[72])(smem_raw + SM_ALO);
    __half (*Bs)[72]   = (__half(*)[72])(smem_raw + SM_B);

    int tid = threadIdx.x;
    if (tid < 64) rows[tid] = (m0 + tid < cnt) ? g_list[e*Tc + m0 + tid] : -1;
    if (tid == 0) {                       // in-block exclusive prefix of g_cnt
        int r = 0;
        for (int i = 0; i < e; i++) r += g_cnt[i];
        s_off = r;
    }
    __syncthreads();

    int warp = tid >> 5;
    int wm = warp & 1, wn = warp >> 1;      // 2x4 warp grid
    wmma::fragment<wmma::accumulator,16,16,16,float>  acc[2][2];
    wmma::fragment<wmma::accumulator,16,16,16,__half> accH[2][2];
    #pragma unroll
    for (int i = 0; i < 2; i++)
        #pragma unroll
        for (int j = 0; j < 2; j++) {
            wmma::fill_fragment(acc[i][j], 0.f);
            wmma::fill_fragment(accH[i][j], __float2half(0.f));
        }

    const __half* W = g_w1q + (size_t)e*DFFc*Dc + (size_t)n0*Dc;

    uint4 pAhi[2], pAlo[2], pB[4];
    {
        int k0 = 0;
        #pragma unroll
        for (int it = 0; it < 2; it++) {
            int u = tid + it*256;
            int r = u >> 3, c = (u & 7) << 3;
            int tok = rows[r] >= 0 ? (rows[r] >> 2) : 0;
            pAhi[it] = *reinterpret_cast<const uint4*>(&g_ctx_hi[(size_t)tok*Dc + k0 + c]);
            pAlo[it] = *reinterpret_cast<const uint4*>(&g_ctx_lo[(size_t)tok*Dc + k0 + c]);
        }
        #pragma unroll
        for (int it = 0; it < 4; it++) {
            int u = tid + it*256;
            int r = u >> 3, c = (u & 7) << 3;
            pB[it] = *reinterpret_cast<const uint4*>(&W[(size_t)r*Dc + k0 + c]);
        }
    }

    for (int k0 = 0; k0 < Dc; k0 += 64) {
        #pragma unroll
        for (int it = 0; it < 2; it++) {
            int u = tid + it*256;
            int r = u >> 3, c = (u & 7) << 3;
            *reinterpret_cast<uint4*>(&AsHi[r][c]) = pAhi[it];
            *reinterpret_cast<uint4*>(&AsLo[r][c]) = pAlo[it];
        }
        #pragma unroll
        for (int it = 0; it < 4; it++) {
            int u = tid + it*256;
            int r = u >> 3, c = (u & 7) << 3;
            *reinterpret_cast<uint4*>(&Bs[r][c]) = pB[it];
        }
        __syncthreads();
        int k1 = k0 + 64;
        if (k1 < Dc) {
            #pragma unroll
            for (int it = 0; it < 2; it++) {
                int u = tid + it*256;
                int r = u >> 3, c = (u & 7) << 3;
                int tok = rows[r] >= 0 ? (rows[r] >> 2) : 0;
                pAhi[it] = *reinterpret_cast<const uint4*>(&g_ctx_hi[(size_t)tok*Dc + k1 + c]);
                pAlo[it] = *reinterpret_cast<const uint4*>(&g_ctx_lo[(size_t)tok*Dc + k1 + c]);
            }
            #pragma unroll
            for (int it = 0; it < 4; it++) {
                int u = tid + it*256;
                int r = u >> 3, c = (u & 7) << 3;
                pB[it] = *reinterpret_cast<const uint4*>(&W[(size_t)r*Dc + k1 + c]);
            }
        }
        #pragma unroll
        for (int kk = 0; kk < 64; kk += 16) {
            wmma::fragment<wmma::matrix_a,16,16,16,__half,wmma::row_major> aHi[2], aLo[2];
            wmma::fragment<wmma::matrix_b,16,16,16,__half,wmma::col_major> b[2];
            #pragma unroll
            for (int i = 0; i < 2; i++) {
                wmma::load_matrix_sync(aHi[i], &AsHi[wm*32 + i*16][kk], 72);
                wmma::load_matrix_sync(aLo[i], &AsLo[wm*32 + i*16][kk], 72);
            }
            #pragma unroll
            for (int j = 0; j < 2; j++)
                wmma::load_matrix_sync(b[j], &Bs[wn*32 + j*16][kk], 72);
            #pragma unroll
            for (int i = 0; i < 2; i++)
                #pragma unroll
                for (int j = 0; j < 2; j++) {
                    wmma::mma_sync(acc[i][j],  aHi[i], b[j], acc[i][j]);
                    wmma::mma_sync(accH[i][j], aLo[i], b[j], accH[i][j]);
                }
        }
        __syncthreads();
    }

    // epilogue via smem
    float  (*Cs)[132]  = (float(*)[132])smem_raw;
    __half (*CsH)[136] = (__half(*)[136])(smem_raw + CSH_OFF);
    #pragma unroll
    for (int i = 0; i < 2; i++)
        #pragma unroll
        for (int j = 0; j < 2; j++) {
            wmma::store_matrix_sync(&Cs[wm*32 + i*16][wn*32 + j*16],  acc[i][j],  132, wmma::mem_row_major);
            wmma::store_matrix_sync(&CsH[wm*32 + i*16][wn*32 + j*16], accH[i][j], 136, wmma::mem_row_major);
        }
    __syncthreads();

    float g1 = g_g1[e];
    int off  = s_off;
    for (int idx = tid; idx < 64*128; idx += 256) {
        int r = idx >> 7, c = idx & 127;
        if (rows[r] < 0) continue;
        float v  = g1 * (Cs[r][c] + __half2float(CsH[r][c]));
        float ge = 0.5f * v * (1.0f + erff(v * 0.7071067811865476f));
        __half hi = __float2half(ge);
        size_t o  = (size_t)(off + m0 + r)*DFFc + n0 + c;
        g_h_hi[o] = hi;
        g_h_lo[o] = __float2half(ge - __half2float(hi));
    }
}

// ---------------- FFN2: O = g2 * H @ W2^T ----------------
__global__ void __launch_bounds__(256, 2) ffn2_kernel() {
    int e   = blockIdx.z;
    int cnt = g_cnt[e];
    int m0  = blockIdx.x * 64;
    if (m0 >= cnt) return;
    int n0  = blockIdx.y * 128;

    __shared__ __align__(16) char smem_raw[SM_BYTES + 64*136*2];
    __shared__ int slots[64];
    __shared__ int s_off;
    __half (*AsHi)[72] = (__half(*)[72])(smem_raw + SM_AHI);
    __half (*AsLo)[72] = (__half(*)[72])(smem_raw + SM_ALO);
    __half (*Bs)[72]   = (__half(*)[72])(smem_raw + SM_B);

    int tid = threadIdx.x;
    if (tid < 64) slots[tid] = (m0 + tid < cnt) ? g_list[e*Tc + m0 + tid] : -1;
    if (tid == 0) {
        int r = 0;
        for (int i = 0; i < e; i++) r += g_cnt[i];
        s_off = r;
    }
    __syncthreads();
    int off = s_off;

    int warp = tid >> 5;
    int wm = warp & 1, wn = warp >> 1;
    wmma::fragment<wmma::accumulator,16,16,16,float>  acc[2][2];
    wmma::fragment<wmma::accumulator,16,16,16,__half> accH[2][2];
    #pragma unroll
    for (int i = 0; i < 2; i++)
        #pragma unroll
        for (int j = 0; j < 2; j++) {
            wmma::fill_fragment(acc[i][j], 0.f);
            wmma::fill_fragment(accH[i][j], __float2half(0.f));
        }

    const __half* W = g_w2q + (size_t)e*DFFc*Dc + (size_t)n0*DFFc;
    int lastrow = off + cnt - 1;

    uint4 pAhi[2], pAlo[2], pB[4];
    {
        int k0 = 0;
        #pragma unroll
        for (int it = 0; it < 2; it++) {
            int u = tid + it*256;
            int r = u >> 3, c = (u & 7) << 3;
            int src = off + m0 + r; if (src > lastrow) src = lastrow;
            pAhi[it] = *reinterpret_cast<const uint4*>(&g_h_hi[(size_t)src*DFFc + k0 + c]);
            pAlo[it] = *reinterpret_cast<const uint4*>(&g_h_lo[(size_t)src*DFFc + k0 + c]);
        }
        #pragma unroll
        for (int it = 0; it < 4; it++) {
            int u = tid + it*256;
            int r = u >> 3, c = (u & 7) << 3;
            pB[it] = *reinterpret_cast<const uint4*>(&W[(size_t)r*DFFc + k0 + c]);
        }
    }

    for (int k0 = 0; k0 < DFFc; k0 += 64) {
        #pragma unroll
        for (int it = 0; it < 2; it++) {
            int u = tid + it*256;
            int r = u >> 3, c = (u & 7) << 3;
            *reinterpret_cast<uint4*>(&AsHi[r][c]) = pAhi[it];
            *reinterpret_cast<uint4*>(&AsLo[r][c]) = pAlo[it];
        }
        #pragma unroll
        for (int it = 0; it < 4; it++) {
            int u = tid + it*256;
            int r = u >> 3, c = (u & 7) << 3;
            *reinterpret_cast<uint4*>(&Bs[r][c]) = pB[it];
        }
        __syncthreads();
        int k1 = k0 + 64;
        if (k1 < DFFc) {
            #pragma unroll
            for (int it = 0; it < 2; it++) {
                int u = tid + it*256;
                int r = u >> 3, c = (u & 7) << 3;
                int src = off + m0 + r; if (src > lastrow) src = lastrow;
                pAhi[it] = *reinterpret_cast<const uint4*>(&g_h_hi[(size_t)src*DFFc + k1 + c]);
                pAlo[it] = *reinterpret_cast<const uint4*>(&g_h_lo[(size_t)src*DFFc + k1 + c]);
            }
            #pragma unroll
            for (int it = 0; it < 4; it++) {
                int u = tid + it*256;
                int r = u >> 3, c = (u & 7) << 3;
                pB[it] = *reinterpret_cast<const uint4*>(&W[(size_t)r*DFFc + k1 + c]);
            }
        }
        #pragma unroll
        for (int kk = 0; kk < 64; kk += 16) {
            wmma::fragment<wmma::matrix_a,16,16,16,__half,wmma::row_major> aHi[2], aLo[2];
            wmma::fragment<wmma::matrix_b,16,16,16,__half,wmma::col_major> b[2];
            #pragma unroll
            for (int i = 0; i < 2; i++) {
                wmma::load_matrix_sync(aHi[i], &AsHi[wm*32 + i*16][kk], 72);
                wmma::load_matrix_sync(aLo[i], &AsLo[wm*32 + i*16][kk], 72);
            }
            #pragma unroll
            for (int j = 0; j < 2; j++)
                wmma::load_matrix_sync(b[j], &Bs[wn*32 + j*16][kk], 72);
            #pragma unroll
            for (int i = 0; i < 2; i++)
                #pragma unroll
                for (int j = 0; j < 2; j++) {
                    wmma::mma_sync(acc[i][j],  aHi[i], b[j], acc[i][j]);
                    wmma::mma_sync(accH[i][j], aLo[i], b[j], accH[i][j]);
                }
        }
        __syncthreads();
    }

    float  (*Cs)[132]  = (float(*)[132])smem_raw;
    __half (*CsH)[136] = (__half(*)[136])(smem_raw + CSH_OFF);
    #pragma unroll
    for (int i = 0; i < 2; i++)
        #pragma unroll
        for (int j = 0; j < 2; j++) {
            wmma::store_matrix_sync(&Cs[wm*32 + i*16][wn*32 + j*16],  acc[i][j],  132, wmma::mem_row_major);
            wmma::store_matrix_sync(&CsH[wm*32 + i*16][wn*32 + j*16], accH[i][j], 136, wmma::mem_row_major);
        }
    __syncthreads();

    float g2 = g_g2[e];
    for (int idx = tid; idx < 64*128; idx += 256) {
        int r = idx >> 7, c = idx & 127;
        int sc = slots[r];
        if (sc < 0) continue;
        g_osl[(size_t)sc*Dc + n0 + c] = g2 * (Cs[r][c] + __half2float(CsH[r][c]));
    }
}

// ---------------- combine (also resets g_cnt for the next step) ----------------
__global__ void combine_kernel(const float* __restrict__ comp, const float* __restrict__ normw) {
    int t = blockIdx.x, tid = threadIdx.x;
    if (t == 0 && tid < Ec) g_cnt[tid] = 0;   // reset for next step's route
    if (!(comp[t] > 0.5f)) return;
    int se[4];
    #pragma unroll
    for (int k = 0; k < 4; k++) se[k] = g_sel[t*4 + k];
    int ord[4] = {0,1,2,3};
    #pragma unroll
    for (int a = 0; a < 3; a++)
        #pragma unroll
        for (int b = a+1; b < 4; b++)
            if (se[ord[b]] < se[ord[a]]) { int tmp = ord[a]; ord[a] = ord[b]; ord[b] = tmp; }
    float y[4]; float ss = 0.f;
    #pragma unroll
    for (int i = 0; i < 4; i++) {
        int d = tid + i*256;
        float s = g_osl[(size_t)(t*4 + ord[0])*Dc + d];
        s += g_osl[(size_t)(t*4 + ord[1])*Dc + d];
        s += g_osl[(size_t)(t*4 + ord[2])*Dc + d];
        s += g_osl[(size_t)(t*4 + ord[3])*Dc + d];
        float v = s + g_state[t*Dc + d];
        y[i] = v; ss += v*v;
    }
    int lane = tid & 31, wp = tid >> 5;
    for (int o = 16; o > 0; o >>= 1) ss += __shfl_down_sync(0xffffffffu, ss, o);
    __shared__ float ws[8];
    __shared__ float svar;
    if (lane == 0) ws[wp] = ss;
    __syncthreads();
    if (tid == 0) {
        float s2 = 0.f;
        for (int w = 0; w < 8; w++) s2 += ws[w];
        svar = s2 * (1.f / (float)Dc);
    }
    __syncthreads();
    float rinv = rsqrtf(svar + 1e-6f);
    #pragma unroll
    for (int i = 0; i < 4; i++) {
        int d = tid + i*256;
        g_state[t*Dc + d] = normw[d] * y[i] * rinv;
    }
}

// ---------------- launch ----------------
extern "C" void kernel_launch(void* const* d_in, const int* in_sizes, int n_in,
                              void* d_out, int out_size) {
    const float* x    = (const float*)d_in[0];
    const float* comp = (const float*)d_in[1];
    const float* gw   = (const float*)d_in[2];
    const float* w1   = (const float*)d_in[3];
    const float* w2   = (const float*)d_in[4];
    const float* temb = (const float*)d_in[5];
    const float* nw   = (const float*)d_in[6];
    float* out = (float*)d_out;

    copy_in_kernel<<<(Tc*Dc + 511)/512, 512>>>(x);

    abs_partial_kernel<<<dim3(1024, 32), 256>>>(w1, w2);
    scales_kernel<<<32, 256>>>();
    gate_kernel<<<1, 256>>>(gw);
    quantw_kernel<<<8192, 256>>>(w1, 0);
    quantw_kernel<<<8192, 256>>>(w2, 1);
    zero_cnt_kernel<<<1, 32>>>();

    for (int s = 0; s < STEPSc; s++) {
        route_kernel<<<Tc, 128>>>(comp, temb, s);
        ffn1_kernel<<<dim3(MBLK, DFFc/128, Ec), 256>>>();
        ffn2_kernel<<<dim3(MBLK, Dc/128, Ec), 256>>>();
        combine_kernel<<<Tc, 256>>>(comp, nw);
    }

    copy_out_kernel<<<(Tc*Dc + 511)/512, 512>>>(out);
}

// round 9
// speedup vs baseline: 1.1410x; 1.0092x over previous
#include <cuda_runtime.h>
#include <cuda_fp16.h>
#include <mma.h>
#include <cstdint>
#include <cstddef>

using namespace nvcuda;

// ---------------- problem constants ----------------
#define Dc     1024
#define DFFc   4096
#define Ec     16
#define TKc    4
#define STEPSc 4
#define Tc     2048
#define RMAXc  (Tc*TKc)
#define PEREXP (DFFc*Dc)
#define MBLK   16                    // m-blocks per expert (cap 1024 rows/expert)

// ---------------- device scratch ----------------
__device__ __half g_w1q[(size_t)Ec*DFFc*Dc];
__device__ __half g_w2q[(size_t)Ec*DFFc*Dc];
__device__ float  g_gateq[Ec*Dc];
__device__ float  g_g1[Ec];
__device__ float  g_g2[Ec];
__device__ float  g_part[32*1024];
__device__ float  g_state[Tc*Dc];
__device__ __half g_ctx_hi[Tc*Dc];
__device__ __half g_ctx_lo[Tc*Dc];
__device__ __half g_h_hi[(size_t)RMAXc*DFFc];
__device__ __half g_h_lo[(size_t)RMAXc*DFFc];
__device__ float  g_osl[(size_t)RMAXc*Dc];
__device__ int    g_list[Ec*Tc];
__device__ int    g_sel[Tc*TKc];
__device__ int    g_cnt[Ec];        // zero-init at load; reset by every combine (replay-safe)

// ---------------- quantization ----------------
__global__ void abs_partial_kernel(const float* __restrict__ w1, const float* __restrict__ w2) {
    int chunk = blockIdx.x;
    int tn    = blockIdx.y;
    const float* base = (tn < Ec) ? (w1 + (size_t)tn * PEREXP)
                                  : (w2 + (size_t)(tn - Ec) * PEREXP);
    base += (size_t)chunk * 4096;
    int tid = threadIdx.x;
    float s = 0.f;
    #pragma unroll
    for (int i = 0; i < 16; i++) s += fabsf(base[tid + i*256]);
    __shared__ float red[256];
    red[tid] = s; __syncthreads();
    for (int st = 128; st > 0; st >>= 1) { if (tid < st) red[tid] += red[tid+st]; __syncthreads(); }
    if (tid == 0) g_part[tn*1024 + chunk] = red[0];
}

// blocks 0..31: per-tensor scales; block 32: ternary gate quantization
__global__ void scales_gate_kernel(const float* __restrict__ gw) {
    int tid = threadIdx.x;
    if (blockIdx.x < 32) {
        int tn = blockIdx.x;
        float s = 0.f;
        for (int i = tid; i < 1024; i += 256) s += g_part[tn*1024 + i];
        __shared__ float red[256];
        red[tid] = s; __syncthreads();
        for (int st = 128; st > 0; st >>= 1) { if (tid < st) red[tid] += red[tid+st]; __syncthreads(); }
        if (tid == 0) {
            float g = fmaxf(red[0] / (float)PEREXP, 1e-5f);
            if (tn < Ec) g_g1[tn] = g; else g_g2[tn - Ec] = g;
        }
    } else {
        float s = 0.f;
        for (int i = tid; i < Ec*Dc; i += 256) s += fabsf(gw[i]);
        __shared__ float red[256];
        __shared__ float sg;
        red[tid] = s; __syncthreads();
        for (int st = 128; st > 0; st >>= 1) { if (tid < st) red[tid] += red[tid+st]; __syncthreads(); }
        if (tid == 0) sg = fmaxf(red[0] / (float)(Ec*Dc), 1e-5f);
        __syncthreads();
        float g = sg;
        for (int i = tid; i < Ec*Dc; i += 256) {
            float q = rintf(gw[i] / g);
            g_gateq[i] = fminf(fmaxf(q, -1.f), 1.f);
        }
    }
}

// quantize BOTH w1 and w2 in one launch
__global__ void quantw_kernel(const float* __restrict__ w1, const float* __restrict__ w2) {
    size_t half   = (size_t)Ec * PEREXP / 4;
    size_t stride = (size_t)gridDim.x * blockDim.x;
    for (size_t i = (size_t)blockIdx.x * blockDim.x + threadIdx.x; i < 2*half; i += stride) {
        int which = i >= half;
        size_t j = which ? i - half : i;
        const float* w = which ? w2 : w1;
        __half* q = which ? g_w2q : g_w1q;
        const float* gs = which ? g_g2 : g_g1;
        int e = (int)((j * 4) / (size_t)PEREXP);
        float g = gs[e];
        float4 v = reinterpret_cast<const float4*>(w)[j];
        float q0 = fminf(fmaxf(rintf(v.x / g), -1.f), 1.f);
        float q1 = fminf(fmaxf(rintf(v.y / g), -1.f), 1.f);
        float q2 = fminf(fmaxf(rintf(v.z / g), -1.f), 1.f);
        float q3 = fminf(fmaxf(rintf(v.w / g), -1.f), 1.f);
        __half2* qo = reinterpret_cast<__half2*>(q) + j*2;
        qo[0] = __floats2half2_rn(q0, q1);
        qo[1] = __floats2half2_rn(q2, q3);
    }
}

// ---------------- routing (step 0 reads x directly) ----------------
__global__ void route_kernel(const float* __restrict__ comp, const float* __restrict__ temb,
                             int step, const float* __restrict__ x) {
    int t = blockIdx.x, tid = threadIdx.x;
    if (!(comp[t] > 0.5f)) {
        #pragma unroll
        for (int i = 0; i < 8; i++) {
            int d = tid + i*128;
            g_ctx_hi[t*Dc + d] = __float2half(0.f);
            g_ctx_lo[t*Dc + d] = __float2half(0.f);
        }
        return;
    }
    const float* src = (step == 0) ? (x + (size_t)t*Dc) : (g_state + (size_t)t*Dc);
    float cx[8];
    #pragma unroll
    for (int i = 0; i < 8; i++) {
        int d = tid + i*128;
        float v = src[d] + temb[step*Dc + d];
        cx[i] = v;
        __half hi = __float2half(v);
        g_ctx_hi[t*Dc + d] = hi;
        g_ctx_lo[t*Dc + d] = __float2half(v - __half2float(hi));
    }
    float p[16];
    #pragma unroll
    for (int e = 0; e < 16; e++) p[e] = 0.f;
    #pragma unroll
    for (int i = 0; i < 8; i++) {
        int d = tid + i*128;
        #pragma unroll
        for (int e = 0; e < 16; e++) p[e] += cx[i] * g_gateq[e*Dc + d];
    }
    __shared__ float wsum[4][16];
    __shared__ float slog[16];
    int lane = tid & 31, wp = tid >> 5;
    #pragma unroll
    for (int e = 0; e < 16; e++) {
        float s = p[e];
        for (int o = 16; o > 0; o >>= 1) s += __shfl_down_sync(0xffffffffu, s, o);
        if (lane == 0) wsum[wp][e] = s;
    }
    __syncthreads();
    if (tid < 16) slog[tid] = wsum[0][tid] + wsum[1][tid] + wsum[2][tid] + wsum[3][tid];
    __syncthreads();
    if (tid == 0) {
        float lg[16];
        #pragma unroll
        for (int e = 0; e < 16; e++) lg[e] = slog[e];
        for (int k = 0; k < TKc; k++) {
            int best = 0; float bv = lg[0];
            for (int e = 1; e < 16; e++) if (lg[e] > bv) { bv = lg[e]; best = e; }
            g_sel[t*TKc + k] = best;
            lg[best] = -3.4e38f;
            int pos = atomicAdd(&g_cnt[best], 1);
            g_list[best*Tc + pos] = t*TKc + k;
        }
    }
}

// ==================================================================
// wmma GEMM (R2 structure): 64(M) x 128(N) block, K-chunk 64,
// 8 warps 2(M)x4(N), warp tile 32x32, register-prefetch double buffer.
// hi pass f32-acc, lo pass f16-acc. smem ~54KB -> 2 CTAs/SM.
// ==================================================================
#define SM_AHI 0
#define SM_ALO 9216
#define SM_B   18432
#define SM_BYTES 36864
#define CSH_OFF  34048

// ---------------- FFN1: H = gelu(g1 * ctx @ W1^T) ----------------
__global__ void __launch_bounds__(256, 2) ffn1_kernel() {
    int e   = blockIdx.z;
    int cnt = g_cnt[e];
    int m0  = blockIdx.x * 64;
    if (m0 >= cnt) return;
    int n0  = blockIdx.y * 128;

    __shared__ __align__(16) char smem_raw[SM_BYTES + 64*136*2];
    __shared__ int rows[64];
    __shared__ int s_off;
    __half (*AsHi)[72] = (__half(*)[72])(smem_raw + SM_AHI);
    __half (*AsLo)[72] = (__half(*)[72])(smem_raw + SM_ALO);
    __half (*Bs)[72]   = (__half(*)[72])(smem_raw + SM_B);

    int tid = threadIdx.x;
    if (tid < 64) rows[tid] = (m0 + tid < cnt) ? g_list[e*Tc + m0 + tid] : -1;
    if (tid == 0) {
        int r = 0;
        for (int i = 0; i < e; i++) r += g_cnt[i];
        s_off = r;
    }
    __syncthreads();

    int warp = tid >> 5;
    int wm = warp & 1, wn = warp >> 1;
    wmma::fragment<wmma::accumulator,16,16,16,float>  acc[2][2];
    wmma::fragment<wmma::accumulator,16,16,16,__half> accH[2][2];
    #pragma unroll
    for (int i = 0; i < 2; i++)
        #pragma unroll
        for (int j = 0; j < 2; j++) {
            wmma::fill_fragment(acc[i][j], 0.f);
            wmma::fill_fragment(accH[i][j], __float2half(0.f));
        }

    const __half* W = g_w1q + (size_t)e*DFFc*Dc + (size_t)n0*Dc;

    uint4 pAhi[2], pAlo[2], pB[4];
    {
        int k0 = 0;
        #pragma unroll
        for (int it = 0; it < 2; it++) {
            int u = tid + it*256;
            int r = u >> 3, c = (u & 7) << 3;
            int tok = rows[r] >= 0 ? (rows[r] >> 2) : 0;
            pAhi[it] = *reinterpret_cast<const uint4*>(&g_ctx_hi[(size_t)tok*Dc + k0 + c]);
            pAlo[it] = *reinterpret_cast<const uint4*>(&g_ctx_lo[(size_t)tok*Dc + k0 + c]);
        }
        #pragma unroll
        for (int it = 0; it < 4; it++) {
            int u = tid + it*256;
            int r = u >> 3, c = (u & 7) << 3;
            pB[it] = *reinterpret_cast<const uint4*>(&W[(size_t)r*Dc + k0 + c]);
        }
    }

    for (int k0 = 0; k0 < Dc; k0 += 64) {
        #pragma unroll
        for (int it = 0; it < 2; it++) {
            int u = tid + it*256;
            int r = u >> 3, c = (u & 7) << 3;
            *reinterpret_cast<uint4*>(&AsHi[r][c]) = pAhi[it];
            *reinterpret_cast<uint4*>(&AsLo[r][c]) = pAlo[it];
        }
        #pragma unroll
        for (int it = 0; it < 4; it++) {
            int u = tid + it*256;
            int r = u >> 3, c = (u & 7) << 3;
            *reinterpret_cast<uint4*>(&Bs[r][c]) = pB[it];
        }
        __syncthreads();
        int k1 = k0 + 64;
        if (k1 < Dc) {
            #pragma unroll
            for (int it = 0; it < 2; it++) {
                int u = tid + it*256;
                int r = u >> 3, c = (u & 7) << 3;
                int tok = rows[r] >= 0 ? (rows[r] >> 2) : 0;
                pAhi[it] = *reinterpret_cast<const uint4*>(&g_ctx_hi[(size_t)tok*Dc + k1 + c]);
                pAlo[it] = *reinterpret_cast<const uint4*>(&g_ctx_lo[(size_t)tok*Dc + k1 + c]);
            }
            #pragma unroll
            for (int it = 0; it < 4; it++) {
                int u = tid + it*256;
                int r = u >> 3, c = (u & 7) << 3;
                pB[it] = *reinterpret_cast<const uint4*>(&W[(size_t)r*Dc + k1 + c]);
            }
        }
        #pragma unroll
        for (int kk = 0; kk < 64; kk += 16) {
            wmma::fragment<wmma::matrix_a,16,16,16,__half,wmma::row_major> aHi[2], aLo[2];
            wmma::fragment<wmma::matrix_b,16,16,16,__half,wmma::col_major> b[2];
            #pragma unroll
            for (int i = 0; i < 2; i++) {
                wmma::load_matrix_sync(aHi[i], &AsHi[wm*32 + i*16][kk], 72);
                wmma::load_matrix_sync(aLo[i], &AsLo[wm*32 + i*16][kk], 72);
            }
            #pragma unroll
            for (int j = 0; j < 2; j++)
                wmma::load_matrix_sync(b[j], &Bs[wn*32 + j*16][kk], 72);
            #pragma unroll
            for (int i = 0; i < 2; i++)
                #pragma unroll
                for (int j = 0; j < 2; j++) {
                    wmma::mma_sync(acc[i][j],  aHi[i], b[j], acc[i][j]);
                    wmma::mma_sync(accH[i][j], aLo[i], b[j], accH[i][j]);
                }
        }
        __syncthreads();
    }

    float  (*Cs)[132]  = (float(*)[132])smem_raw;
    __half (*CsH)[136] = (__half(*)[136])(smem_raw + CSH_OFF);
    #pragma unroll
    for (int i = 0; i < 2; i++)
        #pragma unroll
        for (int j = 0; j < 2; j++) {
            wmma::store_matrix_sync(&Cs[wm*32 + i*16][wn*32 + j*16],  acc[i][j],  132, wmma::mem_row_major);
            wmma::store_matrix_sync(&CsH[wm*32 + i*16][wn*32 + j*16], accH[i][j], 136, wmma::mem_row_major);
        }
    __syncthreads();

    float g1 = g_g1[e];
    int off  = s_off;
    for (int idx = tid; idx < 64*128; idx += 256) {
        int r = idx >> 7, c = idx & 127;
        if (rows[r] < 0) continue;
        float v  = g1 * (Cs[r][c] + __half2float(CsH[r][c]));
        float ge = 0.5f * v * (1.0f + erff(v * 0.7071067811865476f));
        __half hi = __float2half(ge);
        size_t o  = (size_t)(off + m0 + r)*DFFc + n0 + c;
        g_h_hi[o] = hi;
        g_h_lo[o] = __float2half(ge - __half2float(hi));
    }
}

// ---------------- FFN2: O = g2 * H @ W2^T ----------------
__global__ void __launch_bounds__(256, 2) ffn2_kernel() {
    int e   = blockIdx.z;
    int cnt = g_cnt[e];
    int m0  = blockIdx.x * 64;
    if (m0 >= cnt) return;
    int n0  = blockIdx.y * 128;

    __shared__ __align__(16) char smem_raw[SM_BYTES + 64*136*2];
    __shared__ int slots[64];
    __shared__ int s_off;
    __half (*AsHi)[72] = (__half(*)[72])(smem_raw + SM_AHI);
    __half (*AsLo)[72] = (__half(*)[72])(smem_raw + SM_ALO);
    __half (*Bs)[72]   = (__half(*)[72])(smem_raw + SM_B);

    int tid = threadIdx.x;
    if (tid < 64) slots[tid] = (m0 + tid < cnt) ? g_list[e*Tc + m0 + tid] : -1;
    if (tid == 0) {
        int r = 0;
        for (int i = 0; i < e; i++) r += g_cnt[i];
        s_off = r;
    }
    __syncthreads();
    int off = s_off;

    int warp = tid >> 5;
    int wm = warp & 1, wn = warp >> 1;
    wmma::fragment<wmma::accumulator,16,16,16,float>  acc[2][2];
    wmma::fragment<wmma::accumulator,16,16,16,__half> accH[2][2];
    #pragma unroll
    for (int i = 0; i < 2; i++)
        #pragma unroll
        for (int j = 0; j < 2; j++) {
            wmma::fill_fragment(acc[i][j], 0.f);
            wmma::fill_fragment(accH[i][j], __float2half(0.f));
        }

    const __half* W = g_w2q + (size_t)e*DFFc*Dc + (size_t)n0*DFFc;
    int lastrow = off + cnt - 1;

    uint4 pAhi[2], pAlo[2], pB[4];
    {
        int k0 = 0;
        #pragma unroll
        for (int it = 0; it < 2; it++) {
            int u = tid + it*256;
            int r = u >> 3, c = (u & 7) << 3;
            int src = off + m0 + r; if (src > lastrow) src = lastrow;
            pAhi[it] = *reinterpret_cast<const uint4*>(&g_h_hi[(size_t)src*DFFc + k0 + c]);
            pAlo[it] = *reinterpret_cast<const uint4*>(&g_h_lo[(size_t)src*DFFc + k0 + c]);
        }
        #pragma unroll
        for (int it = 0; it < 4; it++) {
            int u = tid + it*256;
            int r = u >> 3, c = (u & 7) << 3;
            pB[it] = *reinterpret_cast<const uint4*>(&W[(size_t)r*DFFc + k0 + c]);
        }
    }

    for (int k0 = 0; k0 < DFFc; k0 += 64) {
        #pragma unroll
        for (int it = 0; it < 2; it++) {
            int u = tid + it*256;
            int r = u >> 3, c = (u & 7) << 3;
            *reinterpret_cast<uint4*>(&AsHi[r][c]) = pAhi[it];
            *reinterpret_cast<uint4*>(&AsLo[r][c]) = pAlo[it];
        }
        #pragma unroll
        for (int it = 0; it < 4; it++) {
            int u = tid + it*256;
            int r = u >> 3, c = (u & 7) << 3;
            *reinterpret_cast<uint4*>(&Bs[r][c]) = pB[it];
        }
        __syncthreads();
        int k1 = k0 + 64;
        if (k1 < DFFc) {
            #pragma unroll
            for (int it = 0; it < 2; it++) {
                int u = tid + it*256;
                int r = u >> 3, c = (u & 7) << 3;
                int src = off + m0 + r; if (src > lastrow) src = lastrow;
                pAhi[it] = *reinterpret_cast<const uint4*>(&g_h_hi[(size_t)src*DFFc + k1 + c]);
                pAlo[it] = *reinterpret_cast<const uint4*>(&g_h_lo[(size_t)src*DFFc + k1 + c]);
            }
            #pragma unroll
            for (int it = 0; it < 4; it++) {
                int u = tid + it*256;
                int r = u >> 3, c = (u & 7) << 3;
                pB[it] = *reinterpret_cast<const uint4*>(&W[(size_t)r*DFFc + k1 + c]);
            }
        }
        #pragma unroll
        for (int kk = 0; kk < 64; kk += 16) {
            wmma::fragment<wmma::matrix_a,16,16,16,__half,wmma::row_major> aHi[2], aLo[2];
            wmma::fragment<wmma::matrix_b,16,16,16,__half,wmma::col_major> b[2];
            #pragma unroll
            for (int i = 0; i < 2; i++) {
                wmma::load_matrix_sync(aHi[i], &AsHi[wm*32 + i*16][kk], 72);
                wmma::load_matrix_sync(aLo[i], &AsLo[wm*32 + i*16][kk], 72);
            }
            #pragma unroll
            for (int j = 0; j < 2; j++)
                wmma::load_matrix_sync(b[j], &Bs[wn*32 + j*16][kk], 72);
            #pragma unroll
            for (int i = 0; i < 2; i++)
                #pragma unroll
                for (int j = 0; j < 2; j++) {
                    wmma::mma_sync(acc[i][j],  aHi[i], b[j], acc[i][j]);
                    wmma::mma_sync(accH[i][j], aLo[i], b[j], accH[i][j]);
                }
        }
        __syncthreads();
    }

    float  (*Cs)[132]  = (float(*)[132])smem_raw;
    __half (*CsH)[136] = (__half(*)[136])(smem_raw + CSH_OFF);
    #pragma unroll
    for (int i = 0; i < 2; i++)
        #pragma unroll
        for (int j = 0; j < 2; j++) {
            wmma::store_matrix_sync(&Cs[wm*32 + i*16][wn*32 + j*16],  acc[i][j],  132, wmma::mem_row_major);
            wmma::store_matrix_sync(&CsH[wm*32 + i*16][wn*32 + j*16], accH[i][j], 136, wmma::mem_row_major);
        }
    __syncthreads();

    float g2 = g_g2[e];
    for (int idx = tid; idx < 64*128; idx += 256) {
        int r = idx >> 7, c = idx & 127;
        int sc = slots[r];
        if (sc < 0) continue;
        g_osl[(size_t)sc*Dc + n0 + c] = g2 * (Cs[r][c] + __half2float(CsH[r][c]));
    }
}

// ---------------- combine (resets g_cnt; final step writes out) ----------------
__global__ void combine_kernel(const float* __restrict__ comp, const float* __restrict__ normw,
                               const float* __restrict__ x, float* __restrict__ out, int is_final) {
    int t = blockIdx.x, tid = threadIdx.x;
    if (t == 0 && tid < Ec) g_cnt[tid] = 0;   // reset for next route (and next graph replay)
    if (!(comp[t] > 0.5f)) {
        if (is_final) {
            #pragma unroll
            for (int i = 0; i < 4; i++) {
                int d = tid + i*256;
                out[(size_t)t*Dc + d] = x[(size_t)t*Dc + d];   // masked: state == original x
            }
        }
        return;
    }
    const float* src = (g_sel[0] == g_sel[0]) ? g_state : g_state;  // keep simple alias
    int se[4];
    #pragma unroll
    for (int k = 0; k < 4; k++) se[k] = g_sel[t*4 + k];
    int ord[4] = {0,1,2,3};
    #pragma unroll
    for (int a = 0; a < 3; a++)
        #pragma unroll
        for (int b = a+1; b < 4; b++)
            if (se[ord[b]] < se[ord[a]]) { int tmp = ord[a]; ord[a] = ord[b]; ord[b] = tmp; }
    float y[4]; float ss = 0.f;
    #pragma unroll
    for (int i = 0; i < 4; i++) {
        int d = tid + i*256;
        float s = g_osl[(size_t)(t*4 + ord[0])*Dc + d];
        s += g_osl[(size_t)(t*4 + ord[1])*Dc + d];
        s += g_osl[(size_t)(t*4 + ord[2])*Dc + d];
        s += g_osl[(size_t)(t*4 + ord[3])*Dc + d];
        float prev = (is_final == 2) ? x[(size_t)t*Dc + d] : src[(size_t)t*Dc + d];
        float v = s + prev;
        y[i] = v; ss += v*v;
    }
    int lane = tid & 31, wp = tid >> 5;
    for (int o = 16; o > 0; o >>= 1) ss += __shfl_down_sync(0xffffffffu, ss, o);
    __shared__ float ws[8];
    __shared__ float svar;
    if (lane == 0) ws[wp] = ss;
    __syncthreads();
    if (tid == 0) {
        float s2 = 0.f;
        for (int w = 0; w < 8; w++) s2 += ws[w];
        svar = s2 * (1.f / (float)Dc);
    }
    __syncthreads();
    float rinv = rsqrtf(svar + 1e-6f);
    #pragma unroll
    for (int i = 0; i < 4; i++) {
        int d = tid + i*256;
        float val = normw[d] * y[i] * rinv;
        if (is_final == 1) out[(size_t)t*Dc + d] = val;        // final: write output only
        else               g_state[(size_t)t*Dc + d] = val;    // intermediate: update state
    }
}

// ---------------- launch ----------------
// is_final codes: 0 = normal step (residual from g_state, write g_state)
//                 1 = final step (residual from g_state, write out)
//                 2 = step 0 (residual from x, write g_state)   [B,S only 4 steps so 0 uses x]
extern "C" void kernel_launch(void* const* d_in, const int* in_sizes, int n_in,
                              void* d_out, int out_size) {
    const float* x    = (const float*)d_in[0];
    const float* comp = (const float*)d_in[1];
    const float* gw   = (const float*)d_in[2];
    const float* w1   = (const float*)d_in[3];
    const float* w2   = (const float*)d_in[4];
    const float* temb = (const float*)d_in[5];
    const float* nw   = (const float*)d_in[6];
    float* out = (float*)d_out;

    abs_partial_kernel<<<dim3(1024, 32), 256>>>(w1, w2);
    scales_gate_kernel<<<33, 256>>>(gw);
    quantw_kernel<<<16384, 256>>>(w1, w2);

    for (int s = 0; s < STEPSc; s++) {
        route_kernel<<<Tc, 128>>>(comp, temb, s, x);
        ffn1_kernel<<<dim3(MBLK, DFFc/128, Ec), 256>>>();
        ffn2_kernel<<<dim3(MBLK, Dc/128, Ec), 256>>>();
        int mode = (s == 0) ? 2 : (s == STEPSc-1 ? 1 : 0);
        combine_kernel<<<Tc, 256>>>(comp, nw, x, out, mode);
    }
}

// round 10
// speedup vs baseline: 1.1610x; 1.0175x over previous
#include <cuda_runtime.h>
#include <cuda_fp16.h>
#include <mma.h>
#include <cstdint>
#include <cstddef>

using namespace nvcuda;

// ---------------- problem constants ----------------
#define Dc     1024
#define DFFc   4096
#define Ec     16
#define TKc    4
#define STEPSc 4
#define Tc     2048
#define RMAXc  (Tc*TKc)
#define PEREXP (DFFc*Dc)
#define MBLK   16                    // m-blocks per expert (cap 1024 rows/expert)

// ---------------- device scratch ----------------
__device__ __half g_w1q[(size_t)Ec*DFFc*Dc];
__device__ __half g_w2q[(size_t)Ec*DFFc*Dc];
__device__ float  g_gateq[Ec*Dc];
__device__ float  g_g1[Ec];
__device__ float  g_g2[Ec];
__device__ float  g_part[32*1024];
__device__ float  g_state[Tc*Dc];
__device__ __half g_ctx_hi[Tc*Dc];
__device__ __half g_ctx_lo[Tc*Dc];
__device__ __half g_h_hi[(size_t)RMAXc*DFFc];
__device__ __half g_h_lo[(size_t)RMAXc*DFFc];
__device__ float  g_osl[(size_t)RMAXc*Dc];
__device__ int    g_list[Ec*Tc];
__device__ int    g_sel[Tc*TKc];
__device__ int    g_cnt[Ec];        // zero at load; reset by every combine (replay-safe)

// ---------------- quantization ----------------
__global__ void abs_partial_kernel(const float* __restrict__ w1, const float* __restrict__ w2) {
    int chunk = blockIdx.x;
    int tn    = blockIdx.y;
    const float* base = (tn < Ec) ? (w1 + (size_t)tn * PEREXP)
                                  : (w2 + (size_t)(tn - Ec) * PEREXP);
    base += (size_t)chunk * 4096;
    int tid = threadIdx.x;
    float s = 0.f;
    #pragma unroll
    for (int i = 0; i < 16; i++) s += fabsf(base[tid + i*256]);
    __shared__ float red[256];
    red[tid] = s; __syncthreads();
    for (int st = 128; st > 0; st >>= 1) { if (tid < st) red[tid] += red[tid+st]; __syncthreads(); }
    if (tid == 0) g_part[tn*1024 + chunk] = red[0];
}

// Fused: blocks 0..16383 quantize (each re-reduces its tensor's scale — identical
// order to the old scales kernel, so scale bits identical); block 16384 = gate.
__global__ void quant_gate_kernel(const float* __restrict__ w1, const float* __restrict__ w2,
                                  const float* __restrict__ gw) {
    int tid = threadIdx.x;
    __shared__ float red[256];
    __shared__ float sg;
    if (blockIdx.x == 16384) {
        float s = 0.f;
        for (int i = tid; i < Ec*Dc; i += 256) s += fabsf(gw[i]);
        red[tid] = s; __syncthreads();
        for (int st = 128; st > 0; st >>= 1) { if (tid < st) red[tid] += red[tid+st]; __syncthreads(); }
        if (tid == 0) sg = fmaxf(red[0] / (float)(Ec*Dc), 1e-5f);
        __syncthreads();
        float g = sg;
        for (int i = tid; i < Ec*Dc; i += 256) {
            float q = rintf(gw[i] / g);
            g_gateq[i] = fminf(fmaxf(q, -1.f), 1.f);
        }
        return;
    }
    int tn  = blockIdx.x >> 9;       // 0..31 (16 w1 tensors, 16 w2 tensors)
    int seg = blockIdx.x & 511;      // 512 segments per tensor
    float s = 0.f;
    for (int i = tid; i < 1024; i += 256) s += g_part[tn*1024 + i];
    red[tid] = s; __syncthreads();
    for (int st = 128; st > 0; st >>= 1) { if (tid < st) red[tid] += red[tid+st]; __syncthreads(); }
    if (tid == 0) {
        sg = fmaxf(red[0] / (float)PEREXP, 1e-5f);
        if (seg == 0) { if (tn < Ec) g_g1[tn] = sg; else g_g2[tn - Ec] = sg; }
    }
    __syncthreads();
    float g = sg;
    int e = tn & 15;
    const float* w = (tn < Ec) ? w1 : w2;
    __half* q      = (tn < Ec) ? g_w1q : g_w2q;
    size_t base = (size_t)e * (PEREXP/4) + (size_t)seg * 2048;   // float4 index
    #pragma unroll
    for (int it = 0; it < 8; it++) {
        size_t i = base + tid + it*256;
        float4 v = reinterpret_cast<const float4*>(w)[i];
        float q0 = fminf(fmaxf(rintf(v.x / g), -1.f), 1.f);
        float q1 = fminf(fmaxf(rintf(v.y / g), -1.f), 1.f);
        float q2 = fminf(fmaxf(rintf(v.z / g), -1.f), 1.f);
        float q3 = fminf(fmaxf(rintf(v.w / g), -1.f), 1.f);
        __half2* qo = reinterpret_cast<__half2*>(q) + i*2;
        qo[0] = __floats2half2_rn(q0, q1);
        qo[1] = __floats2half2_rn(q2, q3);
    }
}

// ---------------- routing (step 0 reads x directly) ----------------
__global__ void route_kernel(const float* __restrict__ comp, const float* __restrict__ temb,
                             int step, const float* __restrict__ x) {
    int t = blockIdx.x, tid = threadIdx.x;
    if (!(comp[t] > 0.5f)) {
        #pragma unroll
        for (int i = 0; i < 8; i++) {
            int d = tid + i*128;
            g_ctx_hi[t*Dc + d] = __float2half(0.f);
            g_ctx_lo[t*Dc + d] = __float2half(0.f);
        }
        return;
    }
    const float* src = (step == 0) ? (x + (size_t)t*Dc) : (g_state + (size_t)t*Dc);
    float cx[8];
    #pragma unroll
    for (int i = 0; i < 8; i++) {
        int d = tid + i*128;
        float v = src[d] + temb[step*Dc + d];
        cx[i] = v;
        __half hi = __float2half(v);
        g_ctx_hi[t*Dc + d] = hi;
        g_ctx_lo[t*Dc + d] = __float2half(v - __half2float(hi));
    }
    float p[16];
    #pragma unroll
    for (int e = 0; e < 16; e++) p[e] = 0.f;
    #pragma unroll
    for (int i = 0; i < 8; i++) {
        int d = tid + i*128;
        #pragma unroll
        for (int e = 0; e < 16; e++) p[e] += cx[i] * g_gateq[e*Dc + d];
    }
    __shared__ float wsum[4][16];
    __shared__ float slog[16];
    int lane = tid & 31, wp = tid >> 5;
    #pragma unroll
    for (int e = 0; e < 16; e++) {
        float s = p[e];
        for (int o = 16; o > 0; o >>= 1) s += __shfl_down_sync(0xffffffffu, s, o);
        if (lane == 0) wsum[wp][e] = s;
    }
    __syncthreads();
    if (tid < 16) slog[tid] = wsum[0][tid] + wsum[1][tid] + wsum[2][tid] + wsum[3][tid];
    __syncthreads();
    if (tid == 0) {
        float lg[16];
        #pragma unroll
        for (int e = 0; e < 16; e++) lg[e] = slog[e];
        for (int k = 0; k < TKc; k++) {
            int best = 0; float bv = lg[0];
            for (int e = 1; e < 16; e++) if (lg[e] > bv) { bv = lg[e]; best = e; }
            g_sel[t*TKc + k] = best;
            lg[best] = -3.4e38f;
            int pos = atomicAdd(&g_cnt[best], 1);
            g_list[best*Tc + pos] = t*TKc + k;
        }
    }
}

// ==================================================================
// wmma GEMM: 64(M)x128(N) block, K-chunk 64, 8 warps 2(M)x4(N),
// warp tile 32x32, split-fp16 A (hi f32-acc, lo f16-acc).
// Double-buffered smem (2x36KB dynamic) + register prefetch:
// ONE __syncthreads per K-chunk. 2 CTAs/SM (144KB smem).
// ==================================================================
#define SM_AHI 0
#define SM_ALO 9216
#define SM_B   18432
#define BUF_BYTES 36864
#define DSM_BYTES (2*BUF_BYTES)      // 73728
#define CSH_OFF   33792              // f16 Cs after f32 Cs (64*132*4)

// ---------------- FFN1: H = gelu(g1 * ctx @ W1^T) ----------------
__global__ void __launch_bounds__(256, 2) ffn1_kernel() {
    extern __shared__ char dsm[];
    __shared__ int rows[64];
    __shared__ int s_off;

    int e   = blockIdx.z;
    int cnt = g_cnt[e];
    int m0  = blockIdx.x * 64;
    if (m0 >= cnt) return;
    int n0  = blockIdx.y * 128;
    int tid = threadIdx.x;

    if (tid < 64) rows[tid] = (m0 + tid < cnt) ? g_list[e*Tc + m0 + tid] : -1;
    if (tid == 0) {
        int r = 0;
        for (int i = 0; i < e; i++) r += g_cnt[i];
        s_off = r;
    }
    __syncthreads();

    const __half* W = g_w1q + (size_t)e*DFFc*Dc + (size_t)n0*Dc;

    int warp = tid >> 5;
    int wm = warp & 1, wn = warp >> 1;
    wmma::fragment<wmma::accumulator,16,16,16,float>  acc[2][2];
    wmma::fragment<wmma::accumulator,16,16,16,__half> accH[2][2];
    #pragma unroll
    for (int i = 0; i < 2; i++)
        #pragma unroll
        for (int j = 0; j < 2; j++) {
            wmma::fill_fragment(acc[i][j], 0.f);
            wmma::fill_fragment(accH[i][j], __float2half(0.f));
        }

    uint4 pAhi[2], pAlo[2], pB[4];

    // prefetch chunk 0 -> regs
    #pragma unroll
    for (int it = 0; it < 2; it++) {
        int u = tid + it*256;
        int r = u >> 3, c = (u & 7) << 3;
        int tok = rows[r] >= 0 ? (rows[r] >> 2) : 0;
        pAhi[it] = *reinterpret_cast<const uint4*>(&g_ctx_hi[(size_t)tok*Dc + c]);
        pAlo[it] = *reinterpret_cast<const uint4*>(&g_ctx_lo[(size_t)tok*Dc + c]);
    }
    #pragma unroll
    for (int it = 0; it < 4; it++) {
        int u = tid + it*256;
        int r = u >> 3, c = (u & 7) << 3;
        pB[it] = *reinterpret_cast<const uint4*>(&W[(size_t)r*Dc + c]);
    }
    // store chunk 0 -> buf0
    {
        char* buf = dsm;
        #pragma unroll
        for (int it = 0; it < 2; it++) {
            int u = tid + it*256;
            int r = u >> 3, c = (u & 7) << 3;
            *reinterpret_cast<uint4*>(buf + SM_AHI + r*144 + c*2) = pAhi[it];
            *reinterpret_cast<uint4*>(buf + SM_ALO + r*144 + c*2) = pAlo[it];
        }
        #pragma unroll
        for (int it = 0; it < 4; it++) {
            int u = tid + it*256;
            int r = u >> 3, c = (u & 7) << 3;
            *reinterpret_cast<uint4*>(buf + SM_B + r*144 + c*2) = pB[it];
        }
    }
    __syncthreads();

    const int KC = Dc / 64;   // 16
    for (int c0 = 0; c0 < KC; c0++) {
        bool more = (c0 + 1 < KC);
        int k1 = (c0 + 1) << 6;
        if (more) {
            #pragma unroll
            for (int it = 0; it < 2; it++) {
                int u = tid + it*256;
                int r = u >> 3, c = (u & 7) << 3;
                int tok = rows[r] >= 0 ? (rows[r] >> 2) : 0;
                pAhi[it] = *reinterpret_cast<const uint4*>(&g_ctx_hi[(size_t)tok*Dc + k1 + c]);
                pAlo[it] = *reinterpret_cast<const uint4*>(&g_ctx_lo[(size_t)tok*Dc + k1 + c]);
            }
            #pragma unroll
            for (int it = 0; it < 4; it++) {
                int u = tid + it*256;
                int r = u >> 3, c = (u & 7) << 3;
                pB[it] = *reinterpret_cast<const uint4*>(&W[(size_t)r*Dc + k1 + c]);
            }
        }
        char* cur = dsm + (size_t)(c0 & 1) * BUF_BYTES;
        __half (*AsHi)[72] = (__half(*)[72])(cur + SM_AHI);
        __half (*AsLo)[72] = (__half(*)[72])(cur + SM_ALO);
        __half (*Bs)[72]   = (__half(*)[72])(cur + SM_B);
        #pragma unroll
        for (int kk = 0; kk < 64; kk += 16) {
            wmma::fragment<wmma::matrix_a,16,16,16,__half,wmma::row_major> aHi[2], aLo[2];
            wmma::fragment<wmma::matrix_b,16,16,16,__half,wmma::col_major> b[2];
            #pragma unroll
            for (int i = 0; i < 2; i++) {
                wmma::load_matrix_sync(aHi[i], &AsHi[wm*32 + i*16][kk], 72);
                wmma::load_matrix_sync(aLo[i], &AsLo[wm*32 + i*16][kk], 72);
            }
            #pragma unroll
            for (int j = 0; j < 2; j++)
                wmma::load_matrix_sync(b[j], &Bs[wn*32 + j*16][kk], 72);
            #pragma unroll
            for (int i = 0; i < 2; i++)
                #pragma unroll
                for (int j = 0; j < 2; j++) {
                    wmma::mma_sync(acc[i][j],  aHi[i], b[j], acc[i][j]);
                    wmma::mma_sync(accH[i][j], aLo[i], b[j], accH[i][j]);
                }
        }
        if (more) {
            char* nxt = dsm + (size_t)((c0 + 1) & 1) * BUF_BYTES;
            #pragma unroll
            for (int it = 0; it < 2; it++) {
                int u = tid + it*256;
                int r = u >> 3, c = (u & 7) << 3;
                *reinterpret_cast<uint4*>(nxt + SM_AHI + r*144 + c*2) = pAhi[it];
                *reinterpret_cast<uint4*>(nxt + SM_ALO + r*144 + c*2) = pAlo[it];
            }
            #pragma unroll
            for (int it = 0; it < 4; it++) {
                int u = tid + it*256;
                int r = u >> 3, c = (u & 7) << 3;
                *reinterpret_cast<uint4*>(nxt + SM_B + r*144 + c*2) = pB[it];
            }
        }
        __syncthreads();
    }

    // epilogue via smem
    float  (*Cs)[132]  = (float(*)[132])dsm;
    __half (*CsH)[136] = (__half(*)[136])(dsm + CSH_OFF);
    #pragma unroll
    for (int i = 0; i < 2; i++)
        #pragma unroll
        for (int j = 0; j < 2; j++) {
            wmma::store_matrix_sync(&Cs[wm*32 + i*16][wn*32 + j*16],  acc[i][j],  132, wmma::mem_row_major);
            wmma::store_matrix_sync(&CsH[wm*32 + i*16][wn*32 + j*16], accH[i][j], 136, wmma::mem_row_major);
        }
    __syncthreads();

    float g1 = g_g1[e];
    int off  = s_off;
    for (int idx = tid; idx < 64*128; idx += 256) {
        int r = idx >> 7, c = idx & 127;
        if (rows[r] < 0) continue;
        float v  = g1 * (Cs[r][c] + __half2float(CsH[r][c]));
        float ge = 0.5f * v * (1.0f + erff(v * 0.7071067811865476f));
        __half hi = __float2half(ge);
        size_t o  = (size_t)(off + m0 + r)*DFFc + n0 + c;
        g_h_hi[o] = hi;
        g_h_lo[o] = __float2half(ge - __half2float(hi));
    }
}

// ---------------- FFN2: O = g2 * H @ W2^T ----------------
__global__ void __launch_bounds__(256, 2) ffn2_kernel() {
    extern __shared__ char dsm[];
    __shared__ int slots[64];
    __shared__ int s_off;

    int e   = blockIdx.z;
    int cnt = g_cnt[e];
    int m0  = blockIdx.x * 64;
    if (m0 >= cnt) return;
    int n0  = blockIdx.y * 128;
    int tid = threadIdx.x;

    if (tid < 64) slots[tid] = (m0 + tid < cnt) ? g_list[e*Tc + m0 + tid] : -1;
    if (tid == 0) {
        int r = 0;
        for (int i = 0; i < e; i++) r += g_cnt[i];
        s_off = r;
    }
    __syncthreads();
    int off = s_off;
    int lastrow = off + cnt - 1;

    const __half* W = g_w2q + (size_t)e*DFFc*Dc + (size_t)n0*DFFc;

    int warp = tid >> 5;
    int wm = warp & 1, wn = warp >> 1;
    wmma::fragment<wmma::accumulator,16,16,16,float>  acc[2][2];
    wmma::fragment<wmma::accumulator,16,16,16,__half> accH[2][2];
    #pragma unroll
    for (int i = 0; i < 2; i++)
        #pragma unroll
        for (int j = 0; j < 2; j++) {
            wmma::fill_fragment(acc[i][j], 0.f);
            wmma::fill_fragment(accH[i][j], __float2half(0.f));
        }

    uint4 pAhi[2], pAlo[2], pB[4];

    #pragma unroll
    for (int it = 0; it < 2; it++) {
        int u = tid + it*256;
        int r = u >> 3, c = (u & 7) << 3;
        int src = off + m0 + r; if (src > lastrow) src = lastrow;
        pAhi[it] = *reinterpret_cast<const uint4*>(&g_h_hi[(size_t)src*DFFc + c]);
        pAlo[it] = *reinterpret_cast<const uint4*>(&g_h_lo[(size_t)src*DFFc + c]);
    }
    #pragma unroll
    for (int it = 0; it < 4; it++) {
        int u = tid + it*256;
        int r = u >> 3, c = (u & 7) << 3;
        pB[it] = *reinterpret_cast<const uint4*>(&W[(size_t)r*DFFc + c]);
    }
    {
        char* buf = dsm;
        #pragma unroll
        for (int it = 0; it < 2; it++) {
            int u = tid + it*256;
            int r = u >> 3, c = (u & 7) << 3;
            *reinterpret_cast<uint4*>(buf + SM_AHI + r*144 + c*2) = pAhi[it];
            *reinterpret_cast<uint4*>(buf + SM_ALO + r*144 + c*2) = pAlo[it];
        }
        #pragma unroll
        for (int it = 0; it < 4; it++) {
            int u = tid + it*256;
            int r = u >> 3, c = (u & 7) << 3;
            *reinterpret_cast<uint4*>(buf + SM_B + r*144 + c*2) = pB[it];
        }
    }
    __syncthreads();

    const int KC = DFFc / 64;   // 64
    for (int c0 = 0; c0 < KC; c0++) {
        bool more = (c0 + 1 < KC);
        int k1 = (c0 + 1) << 6;
        if (more) {
            #pragma unroll
            for (int it = 0; it < 2; it++) {
                int u = tid + it*256;
                int r = u >> 3, c = (u & 7) << 3;
                int src = off + m0 + r; if (src > lastrow) src = lastrow;
                pAhi[it] = *reinterpret_cast<const uint4*>(&g_h_hi[(size_t)src*DFFc + k1 + c]);
                pAlo[it] = *reinterpret_cast<const uint4*>(&g_h_lo[(size_t)src*DFFc + k1 + c]);
            }
            #pragma unroll
            for (int it = 0; it < 4; it++) {
                int u = tid + it*256;
                int r = u >> 3, c = (u & 7) << 3;
                pB[it] = *reinterpret_cast<const uint4*>(&W[(size_t)r*DFFc + k1 + c]);
            }
        }
        char* cur = dsm + (size_t)(c0 & 1) * BUF_BYTES;
        __half (*AsHi)[72] = (__half(*)[72])(cur + SM_AHI);
        __half (*AsLo)[72] = (__half(*)[72])(cur + SM_ALO);
        __half (*Bs)[72]   = (__half(*)[72])(cur + SM_B);
        #pragma unroll
        for (int kk = 0; kk < 64; kk += 16) {
            wmma::fragment<wmma::matrix_a,16,16,16,__half,wmma::row_major> aHi[2], aLo[2];
            wmma::fragment<wmma::matrix_b,16,16,16,__half,wmma::col_major> b[2];
            #pragma unroll
            for (int i = 0; i < 2; i++) {
                wmma::load_matrix_sync(aHi[i], &AsHi[wm*32 + i*16][kk], 72);
                wmma::load_matrix_sync(aLo[i], &AsLo[wm*32 + i*16][kk], 72);
            }
            #pragma unroll
            for (int j = 0; j < 2; j++)
                wmma::load_matrix_sync(b[j], &Bs[wn*32 + j*16][kk], 72);
            #pragma unroll
            for (int i = 0; i < 2; i++)
                #pragma unroll
                for (int j = 0; j < 2; j++) {
                    wmma::mma_sync(acc[i][j],  aHi[i], b[j], acc[i][j]);
                    wmma::mma_sync(accH[i][j], aLo[i], b[j], accH[i][j]);
                }
        }
        if (more) {
            char* nxt = dsm + (size_t)((c0 + 1) & 1) * BUF_BYTES;
            #pragma unroll
            for (int it = 0; it < 2; it++) {
                int u = tid + it*256;
                int r = u >> 3, c = (u & 7) << 3;
                *reinterpret_cast<uint4*>(nxt + SM_AHI + r*144 + c*2) = pAhi[it];
                *reinterpret_cast<uint4*>(nxt + SM_ALO + r*144 + c*2) = pAlo[it];
            }
            #pragma unroll
            for (int it = 0; it < 4; it++) {
                int u = tid + it*256;
                int r = u >> 3, c = (u & 7) << 3;
                *reinterpret_cast<uint4*>(nxt + SM_B + r*144 + c*2) = pB[it];
            }
        }
        __syncthreads();
    }

    float  (*Cs)[132]  = (float(*)[132])dsm;
    __half (*CsH)[136] = (__half(*)[136])(dsm + CSH_OFF);
    #pragma unroll
    for (int i = 0; i < 2; i++)
        #pragma unroll
        for (int j = 0; j < 2; j++) {
            wmma::store_matrix_sync(&Cs[wm*32 + i*16][wn*32 + j*16],  acc[i][j],  132, wmma::mem_row_major);
            wmma::store_matrix_sync(&CsH[wm*32 + i*16][wn*32 + j*16], accH[i][j], 136, wmma::mem_row_major);
        }
    __syncthreads();

    float g2 = g_g2[e];
    for (int idx = tid; idx < 64*128; idx += 256) {
        int r = idx >> 7, c = idx & 127;
        int sc = slots[r];
        if (sc < 0) continue;
        g_osl[(size_t)sc*Dc + n0 + c] = g2 * (Cs[r][c] + __half2float(CsH[r][c]));
    }
}

// ---------------- combine (resets g_cnt; final step writes out) ----------------
__global__ void combine_kernel(const float* __restrict__ comp, const float* __restrict__ normw,
                               const float* __restrict__ x, float* __restrict__ out, int mode) {
    int t = blockIdx.x, tid = threadIdx.x;
    if (t == 0 && tid < Ec) g_cnt[tid] = 0;
    if (!(comp[t] > 0.5f)) {
        if (mode == 1) {
            #pragma unroll
            for (int i = 0; i < 4; i++) {
                int d = tid + i*256;
                out[(size_t)t*Dc + d] = x[(size_t)t*Dc + d];   // masked: state == original x
            }
        }
        return;
    }
    int se[4];
    #pragma unroll
    for (int k = 0; k < 4; k++) se[k] = g_sel[t*4 + k];
    int ord[4] = {0,1,2,3};
    #pragma unroll
    for (int a = 0; a < 3; a++)
        #pragma unroll
        for (int b = a+1; b < 4; b++)
            if (se[ord[b]] < se[ord[a]]) { int tmp = ord[a]; ord[a] = ord[b]; ord[b] = tmp; }
    float y[4]; float ss = 0.f;
    #pragma unroll
    for (int i = 0; i < 4; i++) {
        int d = tid + i*256;
        float s = g_osl[(size_t)(t*4 + ord[0])*Dc + d];
        s += g_osl[(size_t)(t*4 + ord[1])*Dc + d];
        s += g_osl[(size_t)(t*4 + ord[2])*Dc + d];
        s += g_osl[(size_t)(t*4 + ord[3])*Dc + d];
        float prev = (mode == 2) ? x[(size_t)t*Dc + d] : g_state[(size_t)t*Dc + d];
        float v = s + prev;
        y[i] = v; ss += v*v;
    }
    int lane = tid & 31, wp = tid >> 5;
    for (int o = 16; o > 0; o >>= 1) ss += __shfl_down_sync(0xffffffffu, ss, o);
    __shared__ float ws[8];
    __shared__ float svar;
    if (lane == 0) ws[wp] = ss;
    __syncthreads();
    if (tid == 0) {
        float s2 = 0.f;
        for (int w = 0; w < 8; w++) s2 += ws[w];
        svar = s2 * (1.f / (float)Dc);
    }
    __syncthreads();
    float rinv = rsqrtf(svar + 1e-6f);
    #pragma unroll
    for (int i = 0; i < 4; i++) {
        int d = tid + i*256;
        float val = normw[d] * y[i] * rinv;
        if (mode == 1) out[(size_t)t*Dc + d] = val;
        else           g_state[(size_t)t*Dc + d] = val;
    }
}

// ---------------- launch ----------------
// combine mode: 2 = step 0 (residual from x), 0 = middle steps, 1 = final (write out)
extern "C" void kernel_launch(void* const* d_in, const int* in_sizes, int n_in,
                              void* d_out, int out_size) {
    const float* x    = (const float*)d_in[0];
    const float* comp = (const float*)d_in[1];
    const float* gw   = (const float*)d_in[2];
    const float* w1   = (const float*)d_in[3];
    const float* w2   = (const float*)d_in[4];
    const float* temb = (const float*)d_in[5];
    const float* nw   = (const float*)d_in[6];
    float* out = (float*)d_out;

    cudaFuncSetAttribute(ffn1_kernel, cudaFuncAttributeMaxDynamicSharedMemorySize, DSM_BYTES);
    cudaFuncSetAttribute(ffn2_kernel, cudaFuncAttributeMaxDynamicSharedMemorySize, DSM_BYTES);

    abs_partial_kernel<<<dim3(1024, 32), 256>>>(w1, w2);
    quant_gate_kernel<<<16385, 256>>>(w1, w2, gw);

    for (int s = 0; s < STEPSc; s++) {
        route_kernel<<<Tc, 128>>>(comp, temb, s, x);
        ffn1_kernel<<<dim3(MBLK, DFFc/128, Ec), 256, DSM_BYTES>>>();
        ffn2_kernel<<<dim3(MBLK, Dc/128, Ec), 256, DSM_BYTES>>>();
        int mode = (s == 0) ? 2 : (s == STEPSc-1 ? 1 : 0);
        combine_kernel<<<Tc, 256>>>(comp, nw, x, out, mode);
    }
}

// round 12
// speedup vs baseline: 1.2676x; 1.0918x over previous
#include <cuda_runtime.h>
#include <cuda_fp16.h>
#include <mma.h>
#include <cstdint>
#include <cstddef>

using namespace nvcuda;

// ---------------- problem constants ----------------
#define Dc     1024
#define DFFc   4096
#define Ec     16
#define TKc    4
#define STEPSc 4
#define Tc     2048
#define RMAXc  (Tc*TKc)
#define PEREXP (DFFc*Dc)
#define MBLK   16                    // m-blocks per expert (cap 1024 rows/expert)

// ---------------- device scratch ----------------
__device__ __half g_w1q[(size_t)Ec*DFFc*Dc];
__device__ __half g_w2q[(size_t)Ec*DFFc*Dc];
__device__ float  g_gateq[Ec*Dc];
__device__ float  g_g1[Ec];
__device__ float  g_g2[Ec];
__device__ float  g_part[32*1024];
__device__ float  g_state[Tc*Dc];
__device__ __half g_ctx_hi[Tc*Dc];
__device__ __half g_ctx_lo[Tc*Dc];
__device__ __half g_h_hi[(size_t)RMAXc*DFFc];
__device__ __half g_h_lo[(size_t)RMAXc*DFFc];
__device__ float  g_osl[(size_t)RMAXc*Dc];
__device__ int    g_list[Ec*Tc];
__device__ int    g_sel[Tc*TKc];
__device__ int    g_cnt[Ec];        // zero at load; reset by every combine (replay-safe)

// ---------------- async-copy helpers ----------------
__device__ __forceinline__ uint32_t s2u(const void* p) {
    return (uint32_t)__cvta_generic_to_shared(p);
}
#define CP16(dst, src) \
    asm volatile("cp.async.cg.shared.global [%0], [%1], 16;" \
                 :: "r"(dst), "l"((const void*)(src)) : "memory")
#define CP_COMMIT() asm volatile("cp.async.commit_group;" ::: "memory")
#define CP_WAIT0()  asm volatile("cp.async.wait_group 0;" ::: "memory")

// ---------------- quantization ----------------
__global__ void abs_partial_kernel(const float* __restrict__ w1, const float* __restrict__ w2) {
    int chunk = blockIdx.x;
    int tn    = blockIdx.y;
    const float* base = (tn < Ec) ? (w1 + (size_t)tn * PEREXP)
                                  : (w2 + (size_t)(tn - Ec) * PEREXP);
    base += (size_t)chunk * 4096;
    int tid = threadIdx.x;
    float s = 0.f;
    #pragma unroll
    for (int i = 0; i < 16; i++) s += fabsf(base[tid + i*256]);
    __shared__ float red[256];
    red[tid] = s; __syncthreads();
    for (int st = 128; st > 0; st >>= 1) { if (tid < st) red[tid] += red[tid+st]; __syncthreads(); }
    if (tid == 0) g_part[tn*1024 + chunk] = red[0];
}

// Fused: blocks 0..16383 quantize (each re-reduces its tensor's scale); block 16384 = gate.
__global__ void quant_gate_kernel(const float* __restrict__ w1, const float* __restrict__ w2,
                                  const float* __restrict__ gw) {
    int tid = threadIdx.x;
    __shared__ float red[256];
    __shared__ float sg;
    if (blockIdx.x == 16384) {
        float s = 0.f;
        for (int i = tid; i < Ec*Dc; i += 256) s += fabsf(gw[i]);
        red[tid] = s; __syncthreads();
        for (int st = 128; st > 0; st >>= 1) { if (tid < st) red[tid] += red[tid+st]; __syncthreads(); }
        if (tid == 0) sg = fmaxf(red[0] / (float)(Ec*Dc), 1e-5f);
        __syncthreads();
        float g = sg;
        for (int i = tid; i < Ec*Dc; i += 256) {
            float q = rintf(gw[i] / g);
            g_gateq[i] = fminf(fmaxf(q, -1.f), 1.f);
        }
        return;
    }
    int tn  = blockIdx.x >> 9;
    int seg = blockIdx.x & 511;
    float s = 0.f;
    for (int i = tid; i < 1024; i += 256) s += g_part[tn*1024 + i];
    red[tid] = s; __syncthreads();
    for (int st = 128; st > 0; st >>= 1) { if (tid < st) red[tid] += red[tid+st]; __syncthreads(); }
    if (tid == 0) {
        sg = fmaxf(red[0] / (float)PEREXP, 1e-5f);
        if (seg == 0) { if (tn < Ec) g_g1[tn] = sg; else g_g2[tn - Ec] = sg; }
    }
    __syncthreads();
    float g = sg;
    int e = tn & 15;
    const float* w = (tn < Ec) ? w1 : w2;
    __half* q      = (tn < Ec) ? g_w1q : g_w2q;
    size_t base = (size_t)e * (PEREXP/4) + (size_t)seg * 2048;
    #pragma unroll
    for (int it = 0; it < 8; it++) {
        size_t i = base + tid + it*256;
        float4 v = reinterpret_cast<const float4*>(w)[i];
        float q0 = fminf(fmaxf(rintf(v.x / g), -1.f), 1.f);
        float q1 = fminf(fmaxf(rintf(v.y / g), -1.f), 1.f);
        float q2 = fminf(fmaxf(rintf(v.z / g), -1.f), 1.f);
        float q3 = fminf(fmaxf(rintf(v.w / g), -1.f), 1.f);
        __half2* qo = reinterpret_cast<__half2*>(q) + i*2;
        qo[0] = __floats2half2_rn(q0, q1);
        qo[1] = __floats2half2_rn(q2, q3);
    }
}

// ---------------- routing (step 0 reads x directly) ----------------
__global__ void route_kernel(const float* __restrict__ comp, const float* __restrict__ temb,
                             int step, const float* __restrict__ x) {
    int t = blockIdx.x, tid = threadIdx.x;
    if (!(comp[t] > 0.5f)) {
        #pragma unroll
        for (int i = 0; i < 8; i++) {
            int d = tid + i*128;
            g_ctx_hi[t*Dc + d] = __float2half(0.f);
            g_ctx_lo[t*Dc + d] = __float2half(0.f);
        }
        return;
    }
    const float* src = (step == 0) ? (x + (size_t)t*Dc) : (g_state + (size_t)t*Dc);
    float cx[8];
    #pragma unroll
    for (int i = 0; i < 8; i++) {
        int d = tid + i*128;
        float v = src[d] + temb[step*Dc + d];
        cx[i] = v;
        __half hi = __float2half(v);
        g_ctx_hi[t*Dc + d] = hi;
        g_ctx_lo[t*Dc + d] = __float2half(v - __half2float(hi));
    }
    float p[16];
    #pragma unroll
    for (int e = 0; e < 16; e++) p[e] = 0.f;
    #pragma unroll
    for (int i = 0; i < 8; i++) {
        int d = tid + i*128;
        #pragma unroll
        for (int e = 0; e < 16; e++) p[e] += cx[i] * g_gateq[e*Dc + d];
    }
    __shared__ float wsum[4][16];
    __shared__ float slog[16];
    int lane = tid & 31, wp = tid >> 5;
    #pragma unroll
    for (int e = 0; e < 16; e++) {
        float s = p[e];
        for (int o = 16; o > 0; o >>= 1) s += __shfl_down_sync(0xffffffffu, s, o);
        if (lane == 0) wsum[wp][e] = s;
    }
    __syncthreads();
    if (tid < 16) slog[tid] = wsum[0][tid] + wsum[1][tid] + wsum[2][tid] + wsum[3][tid];
    __syncthreads();
    if (tid == 0) {
        float lg[16];
        #pragma unroll
        for (int e = 0; e < 16; e++) lg[e] = slog[e];
        for (int k = 0; k < TKc; k++) {
            int best = 0; float bv = lg[0];
            for (int e = 1; e < 16; e++) if (lg[e] > bv) { bv = lg[e]; best = e; }
            g_sel[t*TKc + k] = best;
            lg[best] = -3.4e38f;
            int pos = atomicAdd(&g_cnt[best], 1);
            g_list[best*Tc + pos] = t*TKc + k;
        }
    }
}

// ==================================================================
// wmma GEMM: 64(M) x 256(N) block tile, K-chunk 64, 8 warps 2(M)x4(N),
// warp tile 32x64 -> 0.5 fragment loads per MMA (was 0.75).
// Both hi and lo limbs accumulate into ONE f32 accumulator set.
// 2-buffer cp.async pipeline, one __syncthreads per chunk.
// Per buffer: AsHi 9216 + AsLo 9216 + Bs 36864 = 55296 B; x2 = 110592.
// 2 CTAs/SM (221 KB smem), target <=128 regs.
// ==================================================================
#define SM_AHI 0
#define SM_ALO 9216
#define SM_B   18432
#define BUF_BYTES 55296
#define DSM_BYTES (2*BUF_BYTES)      // 110592

// ---------------- FFN1: H = gelu(g1 * ctx @ W1^T) ----------------
__global__ void __launch_bounds__(256, 2) ffn1_kernel() {
    extern __shared__ char dsm[];
    __shared__ int rows[64];
    __shared__ int s_off;

    int e   = blockIdx.z;
    int cnt = g_cnt[e];
    int m0  = blockIdx.x * 64;
    if (m0 >= cnt) return;
    int n0  = blockIdx.y * 256;
    int tid = threadIdx.x;

    if (tid < 64) rows[tid] = (m0 + tid < cnt) ? g_list[e*Tc + m0 + tid] : -1;
    if (tid == 0) {
        int r = 0;
        for (int i = 0; i < e; i++) r += g_cnt[i];
        s_off = r;
    }
    __syncthreads();

    const __half* W = g_w1q + (size_t)e*DFFc*Dc + (size_t)n0*Dc;

    // per-thread staging geometry (loop-invariant)
    int ar = tid >> 2, ac = (tid & 3) << 4;        // A: 512 granules/array, 2 iters: u=tid+it*256 -> r=u>>3... keep generic below
    (void)ar; (void)ac;

    auto stage = [&](int chunk, char* buf) {
        int k0 = chunk << 6;
        uint32_t aHi = s2u(buf + SM_AHI);
        uint32_t aLo = s2u(buf + SM_ALO);
        uint32_t bS  = s2u(buf + SM_B);
        #pragma unroll
        for (int it = 0; it < 2; it++) {           // A hi/lo: 64x64 halves = 512 granules each
            int u = tid + (it << 8);
            int r = u >> 3, gi = u & 7;
            uint32_t off = (uint32_t)(r*144 + gi*16);
            int code = rows[r];
            int tok = code >= 0 ? (code >> 2) : 0;
            CP16(aHi + off, g_ctx_hi + (size_t)tok*Dc + k0 + (gi<<3));
            CP16(aLo + off, g_ctx_lo + (size_t)tok*Dc + k0 + (gi<<3));
        }
        #pragma unroll
        for (int it = 0; it < 8; it++) {           // B: 256x64 halves = 2048 granules
            int u = tid + (it << 8);
            int r = u >> 3, gi = u & 7;
            uint32_t off = (uint32_t)(r*144 + gi*16);
            CP16(bS + off, W + (size_t)r*Dc + k0 + (gi<<3));
        }
    };

    int warp = tid >> 5;
    int wm = warp & 1, wn = warp >> 1;             // 2(M) x 4(N); warp tile 32x64
    wmma::fragment<wmma::accumulator,16,16,16,float> acc[2][4];
    #pragma unroll
    for (int i = 0; i < 2; i++)
        #pragma unroll
        for (int j = 0; j < 4; j++) wmma::fill_fragment(acc[i][j], 0.f);

    stage(0, dsm); CP_COMMIT();

    const int KC = Dc / 64;   // 16
    for (int c0 = 0; c0 < KC; c0++) {
        CP_WAIT0();
        __syncthreads();                            // buf[c0&1] ready; prev compute done
        if (c0 + 1 < KC) { stage(c0 + 1, dsm + (size_t)((c0+1)&1)*BUF_BYTES); CP_COMMIT(); }
        char* cur = dsm + (size_t)(c0 & 1) * BUF_BYTES;
        __half (*AsHi)[72] = (__half(*)[72])(cur + SM_AHI);
        __half (*AsLo)[72] = (__half(*)[72])(cur + SM_ALO);
        __half (*Bs)[72]   = (__half(*)[72])(cur + SM_B);
        #pragma unroll
        for (int kk = 0; kk < 64; kk += 16) {
            wmma::fragment<wmma::matrix_a,16,16,16,__half,wmma::row_major> aHi[2], aLo[2];
            #pragma unroll
            for (int i = 0; i < 2; i++) {
                wmma::load_matrix_sync(aHi[i], &AsHi[wm*32 + i*16][kk], 72);
                wmma::load_matrix_sync(aLo[i], &AsLo[wm*32 + i*16][kk], 72);
            }
            #pragma unroll
            for (int j = 0; j < 4; j++) {
                wmma::fragment<wmma::matrix_b,16,16,16,__half,wmma::col_major> b;
                wmma::load_matrix_sync(b, &Bs[wn*64 + j*16][kk], 72);
                #pragma unroll
                for (int i = 0; i < 2; i++) {
                    wmma::mma_sync(acc[i][j], aHi[i], b, acc[i][j]);
                    wmma::mma_sync(acc[i][j], aLo[i], b, acc[i][j]);
                }
            }
        }
    }
    __syncthreads();

    // epilogue via smem: Cs[64][260] f32
    float (*Cs)[260] = (float(*)[260])dsm;
    #pragma unroll
    for (int i = 0; i < 2; i++)
        #pragma unroll
        for (int j = 0; j < 4; j++)
            wmma::store_matrix_sync(&Cs[wm*32 + i*16][wn*64 + j*16], acc[i][j], 260, wmma::mem_row_major);
    __syncthreads();

    float g1 = g_g1[e];
    int off  = s_off;
    for (int idx = tid; idx < 64*256; idx += 256) {
        int r = idx >> 8, c = idx & 255;
        if (rows[r] < 0) continue;
        float v  = g1 * Cs[r][c];
        float ge = 0.5f * v * (1.0f + erff(v * 0.7071067811865476f));
        __half hi = __float2half(ge);
        size_t o  = (size_t)(off + m0 + r)*DFFc + n0 + c;
        g_h_hi[o] = hi;
        g_h_lo[o] = __float2half(ge - __half2float(hi));
    }
}

// ---------------- FFN2: O = g2 * H @ W2^T ----------------
__global__ void __launch_bounds__(256, 2) ffn2_kernel() {
    extern __shared__ char dsm[];
    __shared__ int slots[64];
    __shared__ int s_off;

    int e   = blockIdx.z;
    int cnt = g_cnt[e];
    int m0  = blockIdx.x * 64;
    if (m0 >= cnt) return;
    int n0  = blockIdx.y * 256;
    int tid = threadIdx.x;

    if (tid < 64) slots[tid] = (m0 + tid < cnt) ? g_list[e*Tc + m0 + tid] : -1;
    if (tid == 0) {
        int r = 0;
        for (int i = 0; i < e; i++) r += g_cnt[i];
        s_off = r;
    }
    __syncthreads();
    int off = s_off;
    int lastrow = off + cnt - 1;

    const __half* W = g_w2q + (size_t)e*DFFc*Dc + (size_t)n0*DFFc;

    auto stage = [&](int chunk, char* buf) {
        int k0 = chunk << 6;
        uint32_t aHi = s2u(buf + SM_AHI);
        uint32_t aLo = s2u(buf + SM_ALO);
        uint32_t bS  = s2u(buf + SM_B);
        #pragma unroll
        for (int it = 0; it < 2; it++) {
            int u = tid + (it << 8);
            int r = u >> 3, gi = u & 7;
            uint32_t off2 = (uint32_t)(r*144 + gi*16);
            int src = off + m0 + r; if (src > lastrow) src = lastrow;
            CP16(aHi + off2, g_h_hi + (size_t)src*DFFc + k0 + (gi<<3));
            CP16(aLo + off2, g_h_lo + (size_t)src*DFFc + k0 + (gi<<3));
        }
        #pragma unroll
        for (int it = 0; it < 8; it++) {
            int u = tid + (it << 8);
            int r = u >> 3, gi = u & 7;
            uint32_t off2 = (uint32_t)(r*144 + gi*16);
            CP16(bS + off2, W + (size_t)r*DFFc + k0 + (gi<<3));
        }
    };

    int warp = tid >> 5;
    int wm = warp & 1, wn = warp >> 1;
    wmma::fragment<wmma::accumulator,16,16,16,float> acc[2][4];
    #pragma unroll
    for (int i = 0; i < 2; i++)
        #pragma unroll
        for (int j = 0; j < 4; j++) wmma::fill_fragment(acc[i][j], 0.f);

    stage(0, dsm); CP_COMMIT();

    const int KC = DFFc / 64;   // 64
    for (int c0 = 0; c0 < KC; c0++) {
        CP_WAIT0();
        __syncthreads();
        if (c0 + 1 < KC) { stage(c0 + 1, dsm + (size_t)((c0+1)&1)*BUF_BYTES); CP_COMMIT(); }
        char* cur = dsm + (size_t)(c0 & 1) * BUF_BYTES;
        __half (*AsHi)[72] = (__half(*)[72])(cur + SM_AHI);
        __half (*AsLo)[72] = (__half(*)[72])(cur + SM_ALO);
        __half (*Bs)[72]   = (__half(*)[72])(cur + SM_B);
        #pragma unroll
        for (int kk = 0; kk < 64; kk += 16) {
            wmma::fragment<wmma::matrix_a,16,16,16,__half,wmma::row_major> aHi[2], aLo[2];
            #pragma unroll
            for (int i = 0; i < 2; i++) {
                wmma::load_matrix_sync(aHi[i], &AsHi[wm*32 + i*16][kk], 72);
                wmma::load_matrix_sync(aLo[i], &AsLo[wm*32 + i*16][kk], 72);
            }
            #pragma unroll
            for (int j = 0; j < 4; j++) {
                wmma::fragment<wmma::matrix_b,16,16,16,__half,wmma::col_major> b;
                wmma::load_matrix_sync(b, &Bs[wn*64 + j*16][kk], 72);
                #pragma unroll
                for (int i = 0; i < 2; i++) {
                    wmma::mma_sync(acc[i][j], aHi[i], b, acc[i][j]);
                    wmma::mma_sync(acc[i][j], aLo[i], b, acc[i][j]);
                }
            }
        }
    }
    __syncthreads();

    float (*Cs)[260] = (float(*)[260])dsm;
    #pragma unroll
    for (int i = 0; i < 2; i++)
        #pragma unroll
        for (int j = 0; j < 4; j++)
            wmma::store_matrix_sync(&Cs[wm*32 + i*16][wn*64 + j*16], acc[i][j], 260, wmma::mem_row_major);
    __syncthreads();

    float g2 = g_g2[e];
    for (int idx = tid; idx < 64*256; idx += 256) {
        int r = idx >> 8, c = idx & 255;
        int sc = slots[r];
        if (sc < 0) continue;
        g_osl[(size_t)sc*Dc + n0 + c] = g2 * Cs[r][c];
    }
}

// ---------------- combine (resets g_cnt; final step writes out) ----------------
__global__ void combine_kernel(const float* __restrict__ comp, const float* __restrict__ normw,
                               const float* __restrict__ x, float* __restrict__ out, int mode) {
    int t = blockIdx.x, tid = threadIdx.x;
    if (t == 0 && tid < Ec) g_cnt[tid] = 0;
    if (!(comp[t] > 0.5f)) {
        if (mode == 1) {
            #pragma unroll
            for (int i = 0; i < 4; i++) {
                int d = tid + i*256;
                out[(size_t)t*Dc + d] = x[(size_t)t*Dc + d];
            }
        }
        return;
    }
    int se[4];
    #pragma unroll
    for (int k = 0; k < 4; k++) se[k] = g_sel[t*4 + k];
    int ord[4] = {0,1,2,3};
    #pragma unroll
    for (int a = 0; a < 3; a++)
        #pragma unroll
        for (int b = a+1; b < 4; b++)
            if (se[ord[b]] < se[ord[a]]) { int tmp = ord[a]; ord[a] = ord[b]; ord[b] = tmp; }
    float y[4]; float ss = 0.f;
    #pragma unroll
    for (int i = 0; i < 4; i++) {
        int d = tid + i*256;
        float s = g_osl[(size_t)(t*4 + ord[0])*Dc + d];
        s += g_osl[(size_t)(t*4 + ord[1])*Dc + d];
        s += g_osl[(size_t)(t*4 + ord[2])*Dc + d];
        s += g_osl[(size_t)(t*4 + ord[3])*Dc + d];
        float prev = (mode == 2) ? x[(size_t)t*Dc + d] : g_state[(size_t)t*Dc + d];
        float v = s + prev;
        y[i] = v; ss += v*v;
    }
    int lane = tid & 31, wp = tid >> 5;
    for (int o = 16; o > 0; o >>= 1) ss += __shfl_down_sync(0xffffffffu, ss, o);
    __shared__ float ws[8];
    __shared__ float svar;
    if (lane == 0) ws[wp] = ss;
    __syncthreads();
    if (tid == 0) {
        float s2 = 0.f;
        for (int w = 0; w < 8; w++) s2 += ws[w];
        svar = s2 * (1.f / (float)Dc);
    }
    __syncthreads();
    float rinv = rsqrtf(svar + 1e-6f);
    #pragma unroll
    for (int i = 0; i < 4; i++) {
        int d = tid + i*256;
        float val = normw[d] * y[i] * rinv;
        if (mode == 1) out[(size_t)t*Dc + d] = val;
        else           g_state[(size_t)t*Dc + d] = val;
    }
}

// ---------------- launch ----------------
// combine mode: 2 = step 0 (residual from x), 0 = middle steps, 1 = final (write out)
extern "C" void kernel_launch(void* const* d_in, const int* in_sizes, int n_in,
                              void* d_out, int out_size) {
    const float* x    = (const float*)d_in[0];
    const float* comp = (const float*)d_in[1];
    const float* gw   = (const float*)d_in[2];
    const float* w1   = (const float*)d_in[3];
    const float* w2   = (const float*)d_in[4];
    const float* temb = (const float*)d_in[5];
    const float* nw   = (const float*)d_in[6];
    float* out = (float*)d_out;

    cudaFuncSetAttribute(ffn1_kernel, cudaFuncAttributeMaxDynamicSharedMemorySize, DSM_BYTES);
    cudaFuncSetAttribute(ffn2_kernel, cudaFuncAttributeMaxDynamicSharedMemorySize, DSM_BYTES);

    abs_partial_kernel<<<dim3(1024, 32), 256>>>(w1, w2);
    quant_gate_kernel<<<16385, 256>>>(w1, w2, gw);

    for (int s = 0; s < STEPSc; s++) {
        route_kernel<<<Tc, 128>>>(comp, temb, s, x);
        ffn1_kernel<<<dim3(MBLK, DFFc/256, Ec), 256, DSM_BYTES>>>();
        ffn2_kernel<<<dim3(MBLK, Dc/256, Ec), 256, DSM_BYTES>>>();
        int mode = (s == 0) ? 2 : (s == STEPSc-1 ? 1 : 0);
        combine_kernel<<<Tc, 256>>>(comp, nw, x, out, mode);
    }
}